// round 14
// baseline (speedup 1.0000x reference)
#include <cuda_runtime.h>
#include <cuda_bf16.h>
#include <cstdint>

typedef unsigned long long ull;

constexpr int B_ = 2, T_ = 2048, C_ = 1024, H_ = 16, D_ = 64;
constexpr int BT_ = B_ * T_;   // 4096
constexpr int BH_ = B_ * H_;   // 32
constexpr int AELEM = BT_ * C_;      // 4194304
constexpr int WELEM = C_ * C_;       // 1048576

// ---------------- scratch (static device arrays; no allocation allowed) ----
__device__ float g_q [BT_ * C_];
__device__ float g_k [BT_ * C_];
__device__ float g_v [BT_ * C_];
__device__ float g_qn[BT_ * C_];   // reused: Q bf16 hi|lo planes [BH][T][D]
__device__ float g_kn[BT_ * C_];   // reused: K bf16 hi|lo planes [BH][T][D]
__device__ float g_vn[BT_ * C_];   // reused: V bf16 hi|lo planes [BH][T][D]

__device__ __nv_bfloat16 g_xs [2 * AELEM];      // x  split: hi | lo
__device__ __nv_bfloat16 g_ws [4 * 2 * WELEM];  // Wq,Wk,Wv,Wo: per-matrix hi | lo
__device__ __nv_bfloat16 g_as [2 * AELEM];      // att bf16: hi | lo (from attn epi)

// ---------------- helpers --------------------------------------------------
__device__ __forceinline__ uint32_t smem_u32(const void* p) {
    uint32_t a;
    asm("{ .reg .u64 t; cvta.to.shared.u64 t, %1; cvt.u32.u64 %0, t; }" : "=r"(a) : "l"(p));
    return a;
}

// ==========================================================================
// Split fp32 -> bf16 (hi) + bf16(residual) (lo).  4 elements / thread.
// ==========================================================================
__global__ void __launch_bounds__(256) split_kernel(
    const float4* __restrict__ in, uint2* __restrict__ hi, uint2* __restrict__ lo)
{
    const int i = blockIdx.x * blockDim.x + threadIdx.x;
    float4 f = in[i];
    uint32_t h0, h1;
    asm("cvt.rn.bf16x2.f32 %0, %1, %2;" : "=r"(h0) : "f"(f.y), "f"(f.x));
    asm("cvt.rn.bf16x2.f32 %0, %1, %2;" : "=r"(h1) : "f"(f.w), "f"(f.z));
    float r0 = f.x - __uint_as_float(h0 << 16);
    float r1 = f.y - __uint_as_float(h0 & 0xffff0000u);
    float r2 = f.z - __uint_as_float(h1 << 16);
    float r3 = f.w - __uint_as_float(h1 & 0xffff0000u);
    uint32_t l0, l1;
    asm("cvt.rn.bf16x2.f32 %0, %1, %2;" : "=r"(l0) : "f"(r1), "f"(r0));
    asm("cvt.rn.bf16x2.f32 %0, %1, %2;" : "=r"(l1) : "f"(r3), "f"(r2));
    hi[i] = make_uint2(h0, h1);
    lo[i] = make_uint2(l0, l1);
}

// W splitter: grid.z selects which W; outputs into g_ws + z*2*WELEM.
__global__ void __launch_bounds__(256) split_w_kernel(
    const float* __restrict__ W0, const float* __restrict__ W1,
    const float* __restrict__ W2, const float* __restrict__ W3,
    __nv_bfloat16* __restrict__ ws)
{
    const float* W = (blockIdx.z == 0) ? W0 : (blockIdx.z == 1) ? W1
                   : (blockIdx.z == 2) ? W2 : W3;
    const int i = blockIdx.x * blockDim.x + threadIdx.x;
    float4 f = ((const float4*)W)[i];
    uint32_t h0, h1;
    asm("cvt.rn.bf16x2.f32 %0, %1, %2;" : "=r"(h0) : "f"(f.y), "f"(f.x));
    asm("cvt.rn.bf16x2.f32 %0, %1, %2;" : "=r"(h1) : "f"(f.w), "f"(f.z));
    float r0 = f.x - __uint_as_float(h0 << 16);
    float r1 = f.y - __uint_as_float(h0 & 0xffff0000u);
    float r2 = f.z - __uint_as_float(h1 << 16);
    float r3 = f.w - __uint_as_float(h1 & 0xffff0000u);
    uint32_t l0, l1;
    asm("cvt.rn.bf16x2.f32 %0, %1, %2;" : "=r"(l0) : "f"(r1), "f"(r0));
    asm("cvt.rn.bf16x2.f32 %0, %1, %2;" : "=r"(l1) : "f"(r3), "f"(r2));
    uint2* hi = (uint2*)(ws + (size_t)blockIdx.z * 2 * WELEM);
    uint2* lo = (uint2*)(ws + (size_t)blockIdx.z * 2 * WELEM + WELEM);
    hi[i] = make_uint2(h0, h1);
    lo[i] = make_uint2(l0, l1);
}

// ==========================================================================
// HMMA building blocks (validated R10-R13)
// ==========================================================================
#define CPA16(dst, src) \
    asm volatile("cp.async.cg.shared.global [%0], [%1], 16;" :: "r"(dst), "l"(src))
#define CPA_COMMIT() asm volatile("cp.async.commit_group;" ::: "memory")

#define LDM_X4(r0, r1, r2, r3, a) \
    asm volatile("ldmatrix.sync.aligned.m8n8.x4.shared.b16 {%0,%1,%2,%3}, [%4];" \
                 : "=r"(r0), "=r"(r1), "=r"(r2), "=r"(r3) : "r"(a))

#define LDM_X4_T(r0, r1, r2, r3, a) \
    asm volatile("ldmatrix.sync.aligned.m8n8.x4.trans.shared.b16 {%0,%1,%2,%3}, [%4];" \
                 : "=r"(r0), "=r"(r1), "=r"(r2), "=r"(r3) : "r"(a))

#define MMA16816(c, a, b) \
    asm volatile("mma.sync.aligned.m16n8k16.row.col.f32.bf16.bf16.f32 " \
                 "{%0,%1,%2,%3}, {%4,%5,%6,%7}, {%8,%9}, {%0,%1,%2,%3};" \
                 : "+f"((c)[0]), "+f"((c)[1]), "+f"((c)[2]), "+f"((c)[3]) \
                 : "r"((a)[0]), "r"((a)[1]), "r"((a)[2]), "r"((a)[3]), \
                   "r"((b)[0]), "r"((b)[1]))

// ==========================================================================
// HMMA GEMM (unchanged from R10): O[m,n] = sum_k A[m,k] * W[n,k], bf16x3.
// ==========================================================================
constexpr int GST   = 40;                    // smem row stride (bf16)
constexpr int PLANE = 128 * GST * 2;         // 10240 B
constexpr int GBUF  = 4 * PLANE;             // 40960 B
constexpr int GSMEM = 2 * GBUF;              // 81920 B

__global__ void __launch_bounds__(256) gemm_hmma_kernel(
    const __nv_bfloat16* __restrict__ As,
    const __nv_bfloat16* __restrict__ Ws,
    float* __restrict__ O0, float* __restrict__ O1, float* __restrict__ O2)
{
    extern __shared__ char smem[];
    const uint32_t sb = smem_u32(smem);
    const int tid  = threadIdx.x;
    const int wid  = tid >> 5, lane = tid & 31;
    const int m0   = blockIdx.y * 128;
    const int n0   = blockIdx.x * 128;
    const int wm   = (wid & 1) * 64;
    const int wn   = (wid >> 1) * 32;

    float* O = (blockIdx.z == 0) ? O0 : ((blockIdx.z == 1) ? O1 : O2);
    const __nv_bfloat16* Ah = As;
    const __nv_bfloat16* Al = As + AELEM;
    const __nv_bfloat16* Bh = Ws + (size_t)blockIdx.z * 2 * WELEM;
    const __nv_bfloat16* Bl = Bh + WELEM;

    const int lrow = tid >> 2;
    const int lk8  = (tid & 3) * 8;

    float acc[4][4][4];
#pragma unroll
    for (int i = 0; i < 4; i++)
#pragma unroll
        for (int j = 0; j < 4; j++)
#pragma unroll
            for (int c = 0; c < 4; c++) acc[i][j][c] = 0.0f;

    const uint32_t aBase = (uint32_t)((wm + (lane & 15)) * (GST * 2) + (lane >> 4) * 16);
    const uint32_t bBase = (uint32_t)((wn + (lane & 7) + ((lane >> 4) & 1) * 8) * (GST * 2)
                                      + ((lane >> 3) & 1) * 16);

    auto issue_stage = [&](int kt, int buf) {
        const int k0 = kt * 32;
        const uint32_t dbase = sb + buf * GBUF;
#pragma unroll
        for (int h = 0; h < 2; h++) {
            const int row = lrow + h * 64;
            const uint32_t doff = (uint32_t)(row * (GST * 2) + lk8 * 2);
            CPA16(dbase + 0 * PLANE + doff, Ah + (size_t)(m0 + row) * 1024 + k0 + lk8);
            CPA16(dbase + 1 * PLANE + doff, Al + (size_t)(m0 + row) * 1024 + k0 + lk8);
            CPA16(dbase + 2 * PLANE + doff, Bh + (size_t)(n0 + row) * 1024 + k0 + lk8);
            CPA16(dbase + 3 * PLANE + doff, Bl + (size_t)(n0 + row) * 1024 + k0 + lk8);
        }
        CPA_COMMIT();
    };

    issue_stage(0, 0);

    for (int kt = 0; kt < 32; ++kt) {
        const int buf = kt & 1;
        if (kt + 1 < 32) {
            issue_stage(kt + 1, (kt + 1) & 1);
            asm volatile("cp.async.wait_group 1;" ::: "memory");
        } else {
            asm volatile("cp.async.wait_group 0;" ::: "memory");
        }
        __syncthreads();

        const uint32_t bbase = sb + buf * GBUF;
#pragma unroll
        for (int k16 = 0; k16 < 2; ++k16) {
            const uint32_t ko = (uint32_t)(k16 * 32);
            uint32_t ah[4][4], al[4][4];
#pragma unroll
            for (int i = 0; i < 4; i++) {
                LDM_X4(ah[i][0], ah[i][1], ah[i][2], ah[i][3],
                       bbase + 0 * PLANE + aBase + i * (16 * GST * 2) + ko);
                LDM_X4(al[i][0], al[i][1], al[i][2], al[i][3],
                       bbase + 1 * PLANE + aBase + i * (16 * GST * 2) + ko);
            }
            uint32_t bh[4][2], bl[4][2];
#pragma unroll
            for (int j2 = 0; j2 < 2; j2++) {
                uint32_t r0, r1, r2, r3;
                LDM_X4(r0, r1, r2, r3,
                       bbase + 2 * PLANE + bBase + j2 * (16 * GST * 2) + ko);
                bh[2 * j2][0] = r0; bh[2 * j2][1] = r1;
                bh[2 * j2 + 1][0] = r2; bh[2 * j2 + 1][1] = r3;
                LDM_X4(r0, r1, r2, r3,
                       bbase + 3 * PLANE + bBase + j2 * (16 * GST * 2) + ko);
                bl[2 * j2][0] = r0; bl[2 * j2][1] = r1;
                bl[2 * j2 + 1][0] = r2; bl[2 * j2 + 1][1] = r3;
            }
#pragma unroll
            for (int i = 0; i < 4; i++)
#pragma unroll
                for (int j = 0; j < 4; j++) {
                    MMA16816(acc[i][j], ah[i], bh[j]);
                    MMA16816(acc[i][j], ah[i], bl[j]);
                    MMA16816(acc[i][j], al[i], bh[j]);
                }
        }
        __syncthreads();
    }

    const int r0 = lane >> 2, c0 = (lane & 3) * 2;
#pragma unroll
    for (int i = 0; i < 4; i++) {
#pragma unroll
        for (int j = 0; j < 4; j++) {
            float* p = O + (size_t)(m0 + wm + i * 16 + r0) * 1024 + n0 + wn + j * 8 + c0;
            *(float2*)p = make_float2(acc[i][j][0], acc[i][j][1]);
            *(float2*)(p + 8 * 1024) = make_float2(acc[i][j][2], acc[i][j][3]);
        }
    }
}

// ==========================================================================
// RoPE + L2 norm + scale; emits Q, K, V all as bf16 hi/lo planes [BH][T][D].
// ==========================================================================
__global__ void __launch_bounds__(256) rope_norm_kernel(
    const float* __restrict__ tq, const float* __restrict__ tk, const float* __restrict__ tv,
    const float* __restrict__ sqk,
    __nv_bfloat16* __restrict__ Qp,   // hi plane; lo at +AELEM
    __nv_bfloat16* __restrict__ Kp,
    __nv_bfloat16* __restrict__ Vp)
{
    const int gw   = (blockIdx.x * blockDim.x + threadIdx.x) >> 5;
    const int lane = threadIdx.x & 31;
    const int h  = gw & (H_ - 1);
    const int bt = gw >> 4;
    const int t  = bt & (T_ - 1);
    const int b  = bt >> 11;
    const int p  = lane;

    const size_t src = (size_t)bt * C_ + h * D_ + 2 * p;
    float2 q2 = *(const float2*)(tq + src);
    float2 k2 = *(const float2*)(tk + src);
    float2 v2 = *(const float2*)(tv + src);

    const float ex   = -((float)(2 * p) / (float)D_) * 13.287712379549449f;
    const float invf = exp2f(ex);
    float sn, cs;
    sincosf((float)t * invf, &sn, &cs);

    float2 qr, kr;
    qr.x = q2.x * cs - q2.y * sn;  qr.y = q2.y * cs + q2.x * sn;
    kr.x = k2.x * cs - k2.y * sn;  kr.y = k2.y * cs + k2.x * sn;

    float qs = qr.x * qr.x + qr.y * qr.y;
    float ks = kr.x * kr.x + kr.y * kr.y;
#pragma unroll
    for (int o = 16; o > 0; o >>= 1) {
        qs += __shfl_xor_sync(0xffffffffu, qs, o);
        ks += __shfl_xor_sync(0xffffffffu, ks, o);
    }
    const float qn = fmaxf(sqrtf(qs), 1e-12f);
    const float kn = fmaxf(sqrtf(ks), 1e-12f);

    float2 sc = *(const float2*)(sqk + h * D_ + 2 * p);
    const float iq = (32.0f * 8.0f) / qn;   // s_qk scale 32, sqrt(D)=8 folded in q
    const float ik = 32.0f / kn;

    const float q0 = qr.x * iq * sc.x, q1 = qr.y * iq * sc.y;
    const float k0 = kr.x * ik * sc.x, k1 = kr.y * ik * sc.y;
    const float v0 = v2.x,             v1 = v2.y;

    uint32_t qhi, khi, vhi;
    asm("cvt.rn.bf16x2.f32 %0, %1, %2;" : "=r"(qhi) : "f"(q1), "f"(q0));
    asm("cvt.rn.bf16x2.f32 %0, %1, %2;" : "=r"(khi) : "f"(k1), "f"(k0));
    asm("cvt.rn.bf16x2.f32 %0, %1, %2;" : "=r"(vhi) : "f"(v1), "f"(v0));
    const float qr0 = q0 - __uint_as_float(qhi << 16);
    const float qr1 = q1 - __uint_as_float(qhi & 0xffff0000u);
    const float kr0 = k0 - __uint_as_float(khi << 16);
    const float kr1 = k1 - __uint_as_float(khi & 0xffff0000u);
    const float vr0 = v0 - __uint_as_float(vhi << 16);
    const float vr1 = v1 - __uint_as_float(vhi & 0xffff0000u);
    uint32_t qlo, klo, vlo;
    asm("cvt.rn.bf16x2.f32 %0, %1, %2;" : "=r"(qlo) : "f"(qr1), "f"(qr0));
    asm("cvt.rn.bf16x2.f32 %0, %1, %2;" : "=r"(klo) : "f"(kr1), "f"(kr0));
    asm("cvt.rn.bf16x2.f32 %0, %1, %2;" : "=r"(vlo) : "f"(vr1), "f"(vr0));

    const size_t dst = (((size_t)(b * H_ + h)) * T_ + t) * D_ + 2 * p;
    *(uint32_t*)(Qp + dst)         = qhi;
    *(uint32_t*)(Qp + AELEM + dst) = qlo;
    *(uint32_t*)(Kp + dst)         = khi;
    *(uint32_t*)(Kp + AELEM + dst) = klo;
    *(uint32_t*)(Vp + dst)         = vhi;
    *(uint32_t*)(Vp + AELEM + dst) = vlo;
}

// ==========================================================================
// Flash attention v5: 128-row q-tiles, fully tensorized, fused output split.
//  warps 0-3: S (two m16 sub-blocks each) + softmax, P -> bf16 hi/lo planes.
//  warps 4-7: O += P.V (two m16 sub-blocks each), epilogue emits att as
//             bf16 hi/lo planes directly (Wo GEMM input).
//  K/V hi/lo double-buffered via cp.async.
// ==========================================================================
constexpr int KSTR  = 144;                  // smem row stride bytes (72 bf16)
constexpr int KPL   = 64 * KSTR;            // 9216 B per K/V plane
constexpr int PPL   = 128 * KSTR;           // 18432 B per P plane (128 rows)
constexpr int AT_K0 = 0;                    // K: 2 buf x 2 planes = 36864
constexpr int AT_V0 = 4 * KPL;              // V: 2 buf x 2 planes = 36864
constexpr int AT_P0 = 8 * KPL;              // P: 2 planes = 36864 (Q staged here)
constexpr int AT_AL = AT_P0 + 2 * PPL;      // alphaF: 128 f = 512
constexpr int AT_LI = AT_AL + 512;          // linv: 128 f = 512
constexpr int AT_SM = AT_LI + 512;          // 111616 bytes (2 CTA = 223232 <= 228K)

__global__ void __launch_bounds__(256, 2) attn_kernel(
    const __nv_bfloat16* __restrict__ Qp,   // hi; lo at +AELEM
    const __nv_bfloat16* __restrict__ Kp,
    const __nv_bfloat16* __restrict__ Vp,
    __nv_bfloat16* __restrict__ Yh)         // att bf16 hi; lo at +AELEM, [BT][C]
{
    extern __shared__ char smc[];
    const uint32_t sb = smem_u32(smc);
    float* alphaF = (float*)(smc + AT_AL);
    float* linv   = (float*)(smc + AT_LI);

    const int tid = threadIdx.x;
    const int wid = tid >> 5, lane = tid & 31;

    const int bh = blockIdx.y;
    const int qt = blockIdx.x;              // 0..15 (128 rows each)

    const __nv_bfloat16* Qgh = Qp + ((size_t)bh * T_ + qt * 128) * D_;
    const __nv_bfloat16* Qgl = Qgh + AELEM;
    const __nv_bfloat16* Kgh = Kp + (size_t)bh * T_ * D_;
    const __nv_bfloat16* Kgl = Kgh + AELEM;
    const __nv_bfloat16* Vgh = Vp + (size_t)bh * T_ * D_;
    const __nv_bfloat16* Vgl = Vgh + AELEM;

    // prefetch: K hi/lo + V hi/lo, 2 chunks per plane per thread
    auto issue = [&](int kt) {
        const int bsel = kt & 1;
        const __nv_bfloat16* kh = Kgh + (size_t)kt * 64 * D_;
        const __nv_bfloat16* kl = Kgl + (size_t)kt * 64 * D_;
        const __nv_bfloat16* vh = Vgh + (size_t)kt * 64 * D_;
        const __nv_bfloat16* vl = Vgl + (size_t)kt * 64 * D_;
        const uint32_t kd = sb + AT_K0 + bsel * 2 * KPL;
        const uint32_t vd = sb + AT_V0 + bsel * 2 * KPL;
#pragma unroll
        for (int t = 0; t < 2; t++) {
            const int c = tid + t * 256;
            const int row = c >> 3, o = c & 7;
            const uint32_t off = row * KSTR + o * 16;
            CPA16(kd + off,       kh + row * 64 + o * 8);
            CPA16(kd + KPL + off, kl + row * 64 + o * 8);
            CPA16(vd + off,       vh + row * 64 + o * 8);
            CPA16(vd + KPL + off, vl + row * 64 + o * 8);
        }
        CPA_COMMIT();
    };

    issue(0);

    // stage Q hi/lo (128 rows) into the P region, load frags once
    {
        char* qstg = smc + AT_P0;
#pragma unroll
        for (int t = 0; t < 4; t++) {
            const int c = tid + t * 256;
            const int row = c >> 3, o = c & 7;
            *(uint4*)(qstg + row * KSTR + o * 16) =
                *(const uint4*)(Qgh + row * 64 + o * 8);
            *(uint4*)(qstg + PPL + row * KSTR + o * 16) =
                *(const uint4*)(Qgl + row * 64 + o * 8);
        }
    }
    __syncthreads();

    uint32_t qh[2][4][4], ql[2][4][4];
    if (wid < 4) {
#pragma unroll
        for (int mb = 0; mb < 2; mb++) {
            const uint32_t aaddr = sb + AT_P0
                + (32 * wid + 16 * mb + (lane & 15)) * KSTR + (lane >> 4) * 16;
#pragma unroll
            for (int k16 = 0; k16 < 4; k16++) {
                LDM_X4(qh[mb][k16][0], qh[mb][k16][1], qh[mb][k16][2], qh[mb][k16][3],
                       aaddr + k16 * 32);
                LDM_X4(ql[mb][k16][0], ql[mb][k16][1], ql[mb][k16][2], ql[mb][k16][3],
                       aaddr + PPL + k16 * 32);
            }
        }
    }

    // S-warp softmax state (per sub-block, per row-half)
    float mrun[2][2], lrun[2][2];
#pragma unroll
    for (int mb = 0; mb < 2; mb++) {
        mrun[mb][0] = -3.0e38f; mrun[mb][1] = -3.0e38f;
        lrun[mb][0] = 0.0f;     lrun[mb][1] = 0.0f;
    }
    // PV-warp accumulators: 2 sub-blocks x m16 x d64
    float acc[2][8][4];
#pragma unroll
    for (int mb = 0; mb < 2; mb++)
#pragma unroll
        for (int n = 0; n < 8; n++)
#pragma unroll
            for (int c = 0; c < 4; c++) acc[mb][n][c] = 0.0f;

    // K b-frag (non-trans, validated): lane>>4 -> +8 n-rows, lane>>3 -> +16B k.
    const uint32_t bBase = ((lane & 7) + ((lane >> 4) & 1) * 8) * KSTR
                         + ((lane >> 3) & 1) * 16;
    const int pw = wid - 4;                              // PV warp 0..3
    // V b-frag (trans): lane>>3 -> +8 k-rows, lane>>4 -> +16B d.
    const uint32_t vBase = ((lane & 7) + ((lane >> 3) & 1) * 8) * KSTR
                         + ((lane >> 4) & 1) * 16;

    for (int kt = 0; kt < T_ / 64; kt++) {
        const int buf = kt & 1;
        asm volatile("cp.async.wait_group 0;" ::: "memory");
        __syncthreads();                         // tile kt ready; PV(kt-1) done
        if (kt + 1 < T_ / 64) issue(kt + 1);

        if (wid < 4) {
#pragma unroll
            for (int mb = 0; mb < 2; mb++) {
                // ---- S = Q.K^T : m16n64, 3-term bf16 ----
                float sacc[8][4];
#pragma unroll
                for (int n = 0; n < 8; n++)
#pragma unroll
                    for (int c = 0; c < 4; c++) sacc[n][c] = 0.0f;

                const uint32_t kbase = sb + AT_K0 + buf * 2 * KPL + bBase;
#pragma unroll
                for (int k16 = 0; k16 < 4; k16++) {
                    uint32_t kb[8][2];
#pragma unroll
                    for (int nt = 0; nt < 4; nt++) {
                        uint32_t a0, a1, a2, a3;
                        LDM_X4(a0, a1, a2, a3, kbase + nt * (16 * KSTR) + k16 * 32);
                        kb[2 * nt][0] = a0; kb[2 * nt][1] = a1;
                        kb[2 * nt + 1][0] = a2; kb[2 * nt + 1][1] = a3;
                    }
#pragma unroll
                    for (int n = 0; n < 8; n++) MMA16816(sacc[n], qh[mb][k16], kb[n]);
#pragma unroll
                    for (int n = 0; n < 8; n++) MMA16816(sacc[n], ql[mb][k16], kb[n]);
#pragma unroll
                    for (int nt = 0; nt < 4; nt++) {
                        uint32_t a0, a1, a2, a3;
                        LDM_X4(a0, a1, a2, a3,
                               kbase + KPL + nt * (16 * KSTR) + k16 * 32);
                        kb[2 * nt][0] = a0; kb[2 * nt][1] = a1;
                        kb[2 * nt + 1][0] = a2; kb[2 * nt + 1][1] = a3;
                    }
#pragma unroll
                    for (int n = 0; n < 8; n++) MMA16816(sacc[n], qh[mb][k16], kb[n]);
                }

                // ---- softmax on fragments ----
                const int r0 = 32 * wid + 16 * mb + (lane >> 2);
                const int r1 = r0 + 8;
                float mt0 = sacc[0][0], mt1 = sacc[0][2];
#pragma unroll
                for (int n = 0; n < 8; n++) {
                    mt0 = fmaxf(mt0, fmaxf(sacc[n][0], sacc[n][1]));
                    mt1 = fmaxf(mt1, fmaxf(sacc[n][2], sacc[n][3]));
                }
                mt0 = fmaxf(mt0, __shfl_xor_sync(0xffffffffu, mt0, 1));
                mt0 = fmaxf(mt0, __shfl_xor_sync(0xffffffffu, mt0, 2));
                mt1 = fmaxf(mt1, __shfl_xor_sync(0xffffffffu, mt1, 1));
                mt1 = fmaxf(mt1, __shfl_xor_sync(0xffffffffu, mt1, 2));
                const float mn0 = fmaxf(mrun[mb][0], mt0);
                const float mn1 = fmaxf(mrun[mb][1], mt1);
                const float al0 = __expf(mrun[mb][0] - mn0);
                const float al1 = __expf(mrun[mb][1] - mn1);

                float ps0 = 0.0f, ps1 = 0.0f;
                const int cb = (lane & 3) * 2;
#pragma unroll
                for (int n = 0; n < 8; n++) {
                    const int col = n * 8 + cb;
                    const float p00 = __expf(sacc[n][0] - mn0);
                    const float p01 = __expf(sacc[n][1] - mn0);
                    const float p10 = __expf(sacc[n][2] - mn1);
                    const float p11 = __expf(sacc[n][3] - mn1);
                    ps0 += p00 + p01; ps1 += p10 + p11;
                    uint32_t h0, h1;
                    asm("cvt.rn.bf16x2.f32 %0, %1, %2;" : "=r"(h0) : "f"(p01), "f"(p00));
                    asm("cvt.rn.bf16x2.f32 %0, %1, %2;" : "=r"(h1) : "f"(p11), "f"(p10));
                    const float q00 = p00 - __uint_as_float(h0 << 16);
                    const float q01 = p01 - __uint_as_float(h0 & 0xffff0000u);
                    const float q10 = p10 - __uint_as_float(h1 << 16);
                    const float q11 = p11 - __uint_as_float(h1 & 0xffff0000u);
                    uint32_t l0, l1;
                    asm("cvt.rn.bf16x2.f32 %0, %1, %2;" : "=r"(l0) : "f"(q01), "f"(q00));
                    asm("cvt.rn.bf16x2.f32 %0, %1, %2;" : "=r"(l1) : "f"(q11), "f"(q10));
                    char* pp = smc + AT_P0;
                    *(uint32_t*)(pp + r0 * KSTR + col * 2)       = h0;
                    *(uint32_t*)(pp + r1 * KSTR + col * 2)       = h1;
                    *(uint32_t*)(pp + PPL + r0 * KSTR + col * 2) = l0;
                    *(uint32_t*)(pp + PPL + r1 * KSTR + col * 2) = l1;
                }
                ps0 += __shfl_xor_sync(0xffffffffu, ps0, 1);
                ps0 += __shfl_xor_sync(0xffffffffu, ps0, 2);
                ps1 += __shfl_xor_sync(0xffffffffu, ps1, 1);
                ps1 += __shfl_xor_sync(0xffffffffu, ps1, 2);
                lrun[mb][0] = lrun[mb][0] * al0 + ps0;  mrun[mb][0] = mn0;
                lrun[mb][1] = lrun[mb][1] * al1 + ps1;  mrun[mb][1] = mn1;
                if ((lane & 3) == 0) {
                    alphaF[r0] = al0;
                    alphaF[r1] = al1;
                    if (kt == T_ / 64 - 1) {
                        linv[r0] = 1.0f / lrun[mb][0];
                        linv[r1] = 1.0f / lrun[mb][1];
                    }
                }
            }
        }
        __syncthreads();                         // P, alphaF ready

        if (wid >= 4) {
            const uint32_t vb = sb + AT_V0 + buf * 2 * KPL + vBase;
#pragma unroll
            for (int mb = 0; mb < 2; mb++) {
                const int mrow = 32 * pw + 16 * mb + (lane >> 2);
                const float a0 = alphaF[mrow];
                const float a1 = alphaF[mrow + 8];
#pragma unroll
                for (int n = 0; n < 8; n++) {
                    acc[mb][n][0] *= a0; acc[mb][n][1] *= a0;
                    acc[mb][n][2] *= a1; acc[mb][n][3] *= a1;
                }
                const uint32_t pBase = sb + AT_P0
                    + (32 * pw + 16 * mb + (lane & 15)) * KSTR + (lane >> 4) * 16;
#pragma unroll
                for (int k16 = 0; k16 < 4; k16++) {
                    uint32_t ph[4], pl[4];
                    LDM_X4(ph[0], ph[1], ph[2], ph[3], pBase + k16 * 32);
                    LDM_X4(pl[0], pl[1], pl[2], pl[3], pBase + PPL + k16 * 32);
#pragma unroll
                    for (int d16 = 0; d16 < 4; d16++) {
                        uint32_t vh[4], vl[4];
                        LDM_X4_T(vh[0], vh[1], vh[2], vh[3],
                                 vb + k16 * (16 * KSTR) + d16 * 32);
                        LDM_X4_T(vl[0], vl[1], vl[2], vl[3],
                                 vb + KPL + k16 * (16 * KSTR) + d16 * 32);
                        uint32_t bvh0[2] = { vh[0], vh[1] }, bvh1[2] = { vh[2], vh[3] };
                        uint32_t bvl0[2] = { vl[0], vl[1] }, bvl1[2] = { vl[2], vl[3] };
                        MMA16816(acc[mb][2 * d16],     ph, bvh0);
                        MMA16816(acc[mb][2 * d16 + 1], ph, bvh1);
                        MMA16816(acc[mb][2 * d16],     ph, bvl0);
                        MMA16816(acc[mb][2 * d16 + 1], ph, bvl1);
                        MMA16816(acc[mb][2 * d16],     pl, bvh0);
                        MMA16816(acc[mb][2 * d16 + 1], pl, bvh1);
                    }
                }
            }
        }
    }

    // ---- epilogue (warps 4-7): O * linv -> bf16 hi/lo planes in [BT][C] ----
    if (wid >= 4) {
        const int b = bh >> 4, h = bh & 15;
        const int cb = (lane & 3) * 2;
#pragma unroll
        for (int mb = 0; mb < 2; mb++) {
            const int mrow = 32 * pw + 16 * mb + (lane >> 2);
            const float li0 = linv[mrow];
            const float li1 = linv[mrow + 8];
            const size_t row0 = (size_t)b * T_ + qt * 128 + mrow;
            __nv_bfloat16* d0 = Yh + row0 * C_ + h * D_;
            __nv_bfloat16* d1 = d0 + (size_t)8 * C_;
#pragma unroll
            for (int n = 0; n < 8; n++) {
                const int col = n * 8 + cb;
                const float y00 = acc[mb][n][0] * li0, y01 = acc[mb][n][1] * li0;
                const float y10 = acc[mb][n][2] * li1, y11 = acc[mb][n][3] * li1;
                uint32_t h0, h1;
                asm("cvt.rn.bf16x2.f32 %0, %1, %2;" : "=r"(h0) : "f"(y01), "f"(y00));
                asm("cvt.rn.bf16x2.f32 %0, %1, %2;" : "=r"(h1) : "f"(y11), "f"(y10));
                const float z00 = y00 - __uint_as_float(h0 << 16);
                const float z01 = y01 - __uint_as_float(h0 & 0xffff0000u);
                const float z10 = y10 - __uint_as_float(h1 << 16);
                const float z11 = y11 - __uint_as_float(h1 & 0xffff0000u);
                uint32_t l0, l1;
                asm("cvt.rn.bf16x2.f32 %0, %1, %2;" : "=r"(l0) : "f"(z01), "f"(z00));
                asm("cvt.rn.bf16x2.f32 %0, %1, %2;" : "=r"(l1) : "f"(z11), "f"(z10));
                *(uint32_t*)(d0 + col)         = h0;
                *(uint32_t*)(d0 + AELEM + col) = l0;
                *(uint32_t*)(d1 + col)         = h1;
                *(uint32_t*)(d1 + AELEM + col) = l1;
            }
        }
    }
}

// ==========================================================================
extern "C" void kernel_launch(void* const* d_in, const int* in_sizes, int n_in,
                              void* d_out, int out_size)
{
    const float* x   = (const float*)d_in[0];
    const float* Wq  = (const float*)d_in[1];
    const float* Wk  = (const float*)d_in[2];
    const float* Wv  = (const float*)d_in[3];
    const float* Wo  = (const float*)d_in[4];
    const float* sqk = (const float*)d_in[5];
    float* out = (float*)d_out;

    static float *q = nullptr, *k, *v, *qn, *kn, *vn;
    static __nv_bfloat16 *xs, *ws, *as;
    static bool init_done = false;
    if (!init_done) {
        cudaGetSymbolAddress((void**)&q,   g_q);
        cudaGetSymbolAddress((void**)&k,   g_k);
        cudaGetSymbolAddress((void**)&v,   g_v);
        cudaGetSymbolAddress((void**)&qn,  g_qn);
        cudaGetSymbolAddress((void**)&kn,  g_kn);
        cudaGetSymbolAddress((void**)&vn,  g_vn);
        cudaGetSymbolAddress((void**)&xs,  g_xs);
        cudaGetSymbolAddress((void**)&ws,  g_ws);
        cudaGetSymbolAddress((void**)&as,  g_as);
        cudaFuncSetAttribute(attn_kernel,
                             cudaFuncAttributeMaxDynamicSharedMemorySize, AT_SM);
        cudaFuncSetAttribute(gemm_hmma_kernel,
                             cudaFuncAttributeMaxDynamicSharedMemorySize, GSMEM);
        init_done = true;
    }

    // split x and the 4 weight matrices to bf16 hi/lo planes
    split_kernel<<<AELEM / 4 / 256, 256>>>((const float4*)x, (uint2*)xs,
                                           (uint2*)(xs + AELEM));
    split_w_kernel<<<dim3(WELEM / 4 / 256, 1, 4), 256>>>(Wq, Wk, Wv, Wo, ws);

    // QKV projections on HMMA (bf16x3)
    gemm_hmma_kernel<<<dim3(8, 32, 3), 256, GSMEM>>>(xs, ws, q, k, v);

    // RoPE + norm; Q/K/V emitted as bf16 hi/lo planes
    rope_norm_kernel<<<(BT_ * H_) / 8, 256>>>(
        q, k, v, sqk, (__nv_bfloat16*)qn, (__nv_bfloat16*)kn, (__nv_bfloat16*)vn);

    // Flash attention (S and PV on HMMA bf16x3, 128-row q-tiles,
    // epilogue emits att directly as bf16 hi/lo planes)
    attn_kernel<<<dim3(T_ / 128, BH_), 256, AT_SM>>>(
        (const __nv_bfloat16*)qn, (const __nv_bfloat16*)kn,
        (const __nv_bfloat16*)vn, as);

    // Wo projection on HMMA (att split already fused into attention epilogue)
    gemm_hmma_kernel<<<dim3(8, 32, 1), 256, GSMEM>>>(as, ws + (size_t)3 * 2 * WELEM,
                                                     out, out, out);
}

// round 15
// speedup vs baseline: 1.2629x; 1.2629x over previous
#include <cuda_runtime.h>
#include <cuda_bf16.h>
#include <cstdint>

typedef unsigned long long ull;

constexpr int B_ = 2, T_ = 2048, C_ = 1024, H_ = 16, D_ = 64;
constexpr int BT_ = B_ * T_;   // 4096
constexpr int BH_ = B_ * H_;   // 32
constexpr int AELEM = BT_ * C_;      // 4194304
constexpr int WELEM = C_ * C_;       // 1048576

// ---------------- scratch (static device arrays; no allocation allowed) ----
__device__ float g_q [BT_ * C_];
__device__ float g_k [BT_ * C_];
__device__ float g_v [BT_ * C_];
__device__ float g_qn[BT_ * C_];   // reused: Q bf16 hi|lo planes [BH][T][D]
__device__ float g_kn[BT_ * C_];   // reused: K bf16 hi|lo planes [BH][T][D]
__device__ float g_vn[BT_ * C_];   // reused: V bf16 hi|lo planes [BH][T][D]

__device__ __nv_bfloat16 g_xs [2 * AELEM];      // x  split: hi | lo
__device__ __nv_bfloat16 g_ws [4 * 2 * WELEM];  // Wq,Wk,Wv,Wo: per-matrix hi | lo
__device__ __nv_bfloat16 g_as [2 * AELEM];      // att bf16: hi | lo (from attn epi)

// ---------------- helpers --------------------------------------------------
__device__ __forceinline__ uint32_t smem_u32(const void* p) {
    uint32_t a;
    asm("{ .reg .u64 t; cvta.to.shared.u64 t, %1; cvt.u32.u64 %0, t; }" : "=r"(a) : "l"(p));
    return a;
}

// ==========================================================================
// Split fp32 -> bf16 (hi) + bf16(residual) (lo).  4 elements / thread.
// ==========================================================================
__global__ void __launch_bounds__(256) split_kernel(
    const float4* __restrict__ in, uint2* __restrict__ hi, uint2* __restrict__ lo)
{
    const int i = blockIdx.x * blockDim.x + threadIdx.x;
    float4 f = in[i];
    uint32_t h0, h1;
    asm("cvt.rn.bf16x2.f32 %0, %1, %2;" : "=r"(h0) : "f"(f.y), "f"(f.x));
    asm("cvt.rn.bf16x2.f32 %0, %1, %2;" : "=r"(h1) : "f"(f.w), "f"(f.z));
    float r0 = f.x - __uint_as_float(h0 << 16);
    float r1 = f.y - __uint_as_float(h0 & 0xffff0000u);
    float r2 = f.z - __uint_as_float(h1 << 16);
    float r3 = f.w - __uint_as_float(h1 & 0xffff0000u);
    uint32_t l0, l1;
    asm("cvt.rn.bf16x2.f32 %0, %1, %2;" : "=r"(l0) : "f"(r1), "f"(r0));
    asm("cvt.rn.bf16x2.f32 %0, %1, %2;" : "=r"(l1) : "f"(r3), "f"(r2));
    hi[i] = make_uint2(h0, h1);
    lo[i] = make_uint2(l0, l1);
}

// W splitter: grid.z selects which W; outputs into g_ws + z*2*WELEM.
__global__ void __launch_bounds__(256) split_w_kernel(
    const float* __restrict__ W0, const float* __restrict__ W1,
    const float* __restrict__ W2, const float* __restrict__ W3,
    __nv_bfloat16* __restrict__ ws)
{
    const float* W = (blockIdx.z == 0) ? W0 : (blockIdx.z == 1) ? W1
                   : (blockIdx.z == 2) ? W2 : W3;
    const int i = blockIdx.x * blockDim.x + threadIdx.x;
    float4 f = ((const float4*)W)[i];
    uint32_t h0, h1;
    asm("cvt.rn.bf16x2.f32 %0, %1, %2;" : "=r"(h0) : "f"(f.y), "f"(f.x));
    asm("cvt.rn.bf16x2.f32 %0, %1, %2;" : "=r"(h1) : "f"(f.w), "f"(f.z));
    float r0 = f.x - __uint_as_float(h0 << 16);
    float r1 = f.y - __uint_as_float(h0 & 0xffff0000u);
    float r2 = f.z - __uint_as_float(h1 << 16);
    float r3 = f.w - __uint_as_float(h1 & 0xffff0000u);
    uint32_t l0, l1;
    asm("cvt.rn.bf16x2.f32 %0, %1, %2;" : "=r"(l0) : "f"(r1), "f"(r0));
    asm("cvt.rn.bf16x2.f32 %0, %1, %2;" : "=r"(l1) : "f"(r3), "f"(r2));
    uint2* hi = (uint2*)(ws + (size_t)blockIdx.z * 2 * WELEM);
    uint2* lo = (uint2*)(ws + (size_t)blockIdx.z * 2 * WELEM + WELEM);
    hi[i] = make_uint2(h0, h1);
    lo[i] = make_uint2(l0, l1);
}

// ==========================================================================
// HMMA building blocks (validated R10-R13)
// ==========================================================================
#define CPA16(dst, src) \
    asm volatile("cp.async.cg.shared.global [%0], [%1], 16;" :: "r"(dst), "l"(src))
#define CPA_COMMIT() asm volatile("cp.async.commit_group;" ::: "memory")

#define LDM_X4(r0, r1, r2, r3, a) \
    asm volatile("ldmatrix.sync.aligned.m8n8.x4.shared.b16 {%0,%1,%2,%3}, [%4];" \
                 : "=r"(r0), "=r"(r1), "=r"(r2), "=r"(r3) : "r"(a))

#define LDM_X4_T(r0, r1, r2, r3, a) \
    asm volatile("ldmatrix.sync.aligned.m8n8.x4.trans.shared.b16 {%0,%1,%2,%3}, [%4];" \
                 : "=r"(r0), "=r"(r1), "=r"(r2), "=r"(r3) : "r"(a))

#define MMA16816(c, a, b) \
    asm volatile("mma.sync.aligned.m16n8k16.row.col.f32.bf16.bf16.f32 " \
                 "{%0,%1,%2,%3}, {%4,%5,%6,%7}, {%8,%9}, {%0,%1,%2,%3};" \
                 : "+f"((c)[0]), "+f"((c)[1]), "+f"((c)[2]), "+f"((c)[3]) \
                 : "r"((a)[0]), "r"((a)[1]), "r"((a)[2]), "r"((a)[3]), \
                   "r"((b)[0]), "r"((b)[1]))

// ==========================================================================
// HMMA GEMM (unchanged from R10): O[m,n] = sum_k A[m,k] * W[n,k], bf16x3.
// ==========================================================================
constexpr int GST   = 40;                    // smem row stride (bf16)
constexpr int PLANE = 128 * GST * 2;         // 10240 B
constexpr int GBUF  = 4 * PLANE;             // 40960 B
constexpr int GSMEM = 2 * GBUF;              // 81920 B

__global__ void __launch_bounds__(256) gemm_hmma_kernel(
    const __nv_bfloat16* __restrict__ As,
    const __nv_bfloat16* __restrict__ Ws,
    float* __restrict__ O0, float* __restrict__ O1, float* __restrict__ O2)
{
    extern __shared__ char smem[];
    const uint32_t sb = smem_u32(smem);
    const int tid  = threadIdx.x;
    const int wid  = tid >> 5, lane = tid & 31;
    const int m0   = blockIdx.y * 128;
    const int n0   = blockIdx.x * 128;
    const int wm   = (wid & 1) * 64;
    const int wn   = (wid >> 1) * 32;

    float* O = (blockIdx.z == 0) ? O0 : ((blockIdx.z == 1) ? O1 : O2);
    const __nv_bfloat16* Ah = As;
    const __nv_bfloat16* Al = As + AELEM;
    const __nv_bfloat16* Bh = Ws + (size_t)blockIdx.z * 2 * WELEM;
    const __nv_bfloat16* Bl = Bh + WELEM;

    const int lrow = tid >> 2;
    const int lk8  = (tid & 3) * 8;

    float acc[4][4][4];
#pragma unroll
    for (int i = 0; i < 4; i++)
#pragma unroll
        for (int j = 0; j < 4; j++)
#pragma unroll
            for (int c = 0; c < 4; c++) acc[i][j][c] = 0.0f;

    const uint32_t aBase = (uint32_t)((wm + (lane & 15)) * (GST * 2) + (lane >> 4) * 16);
    const uint32_t bBase = (uint32_t)((wn + (lane & 7) + ((lane >> 4) & 1) * 8) * (GST * 2)
                                      + ((lane >> 3) & 1) * 16);

    auto issue_stage = [&](int kt, int buf) {
        const int k0 = kt * 32;
        const uint32_t dbase = sb + buf * GBUF;
#pragma unroll
        for (int h = 0; h < 2; h++) {
            const int row = lrow + h * 64;
            const uint32_t doff = (uint32_t)(row * (GST * 2) + lk8 * 2);
            CPA16(dbase + 0 * PLANE + doff, Ah + (size_t)(m0 + row) * 1024 + k0 + lk8);
            CPA16(dbase + 1 * PLANE + doff, Al + (size_t)(m0 + row) * 1024 + k0 + lk8);
            CPA16(dbase + 2 * PLANE + doff, Bh + (size_t)(n0 + row) * 1024 + k0 + lk8);
            CPA16(dbase + 3 * PLANE + doff, Bl + (size_t)(n0 + row) * 1024 + k0 + lk8);
        }
        CPA_COMMIT();
    };

    issue_stage(0, 0);

    for (int kt = 0; kt < 32; ++kt) {
        const int buf = kt & 1;
        if (kt + 1 < 32) {
            issue_stage(kt + 1, (kt + 1) & 1);
            asm volatile("cp.async.wait_group 1;" ::: "memory");
        } else {
            asm volatile("cp.async.wait_group 0;" ::: "memory");
        }
        __syncthreads();

        const uint32_t bbase = sb + buf * GBUF;
#pragma unroll
        for (int k16 = 0; k16 < 2; ++k16) {
            const uint32_t ko = (uint32_t)(k16 * 32);
            uint32_t ah[4][4], al[4][4];
#pragma unroll
            for (int i = 0; i < 4; i++) {
                LDM_X4(ah[i][0], ah[i][1], ah[i][2], ah[i][3],
                       bbase + 0 * PLANE + aBase + i * (16 * GST * 2) + ko);
                LDM_X4(al[i][0], al[i][1], al[i][2], al[i][3],
                       bbase + 1 * PLANE + aBase + i * (16 * GST * 2) + ko);
            }
            uint32_t bh[4][2], bl[4][2];
#pragma unroll
            for (int j2 = 0; j2 < 2; j2++) {
                uint32_t r0, r1, r2, r3;
                LDM_X4(r0, r1, r2, r3,
                       bbase + 2 * PLANE + bBase + j2 * (16 * GST * 2) + ko);
                bh[2 * j2][0] = r0; bh[2 * j2][1] = r1;
                bh[2 * j2 + 1][0] = r2; bh[2 * j2 + 1][1] = r3;
                LDM_X4(r0, r1, r2, r3,
                       bbase + 3 * PLANE + bBase + j2 * (16 * GST * 2) + ko);
                bl[2 * j2][0] = r0; bl[2 * j2][1] = r1;
                bl[2 * j2 + 1][0] = r2; bl[2 * j2 + 1][1] = r3;
            }
#pragma unroll
            for (int i = 0; i < 4; i++)
#pragma unroll
                for (int j = 0; j < 4; j++) {
                    MMA16816(acc[i][j], ah[i], bh[j]);
                    MMA16816(acc[i][j], ah[i], bl[j]);
                    MMA16816(acc[i][j], al[i], bh[j]);
                }
        }
        __syncthreads();
    }

    const int r0 = lane >> 2, c0 = (lane & 3) * 2;
#pragma unroll
    for (int i = 0; i < 4; i++) {
#pragma unroll
        for (int j = 0; j < 4; j++) {
            float* p = O + (size_t)(m0 + wm + i * 16 + r0) * 1024 + n0 + wn + j * 8 + c0;
            *(float2*)p = make_float2(acc[i][j][0], acc[i][j][1]);
            *(float2*)(p + 8 * 1024) = make_float2(acc[i][j][2], acc[i][j][3]);
        }
    }
}

// ==========================================================================
// RoPE + L2 norm + scale; emits Q, K, V all as bf16 hi/lo planes [BH][T][D].
// ==========================================================================
__global__ void __launch_bounds__(256) rope_norm_kernel(
    const float* __restrict__ tq, const float* __restrict__ tk, const float* __restrict__ tv,
    const float* __restrict__ sqk,
    __nv_bfloat16* __restrict__ Qp,   // hi plane; lo at +AELEM
    __nv_bfloat16* __restrict__ Kp,
    __nv_bfloat16* __restrict__ Vp)
{
    const int gw   = (blockIdx.x * blockDim.x + threadIdx.x) >> 5;
    const int lane = threadIdx.x & 31;
    const int h  = gw & (H_ - 1);
    const int bt = gw >> 4;
    const int t  = bt & (T_ - 1);
    const int b  = bt >> 11;
    const int p  = lane;

    const size_t src = (size_t)bt * C_ + h * D_ + 2 * p;
    float2 q2 = *(const float2*)(tq + src);
    float2 k2 = *(const float2*)(tk + src);
    float2 v2 = *(const float2*)(tv + src);

    const float ex   = -((float)(2 * p) / (float)D_) * 13.287712379549449f;
    const float invf = exp2f(ex);
    float sn, cs;
    sincosf((float)t * invf, &sn, &cs);

    float2 qr, kr;
    qr.x = q2.x * cs - q2.y * sn;  qr.y = q2.y * cs + q2.x * sn;
    kr.x = k2.x * cs - k2.y * sn;  kr.y = k2.y * cs + k2.x * sn;

    float qs = qr.x * qr.x + qr.y * qr.y;
    float ks = kr.x * kr.x + kr.y * kr.y;
#pragma unroll
    for (int o = 16; o > 0; o >>= 1) {
        qs += __shfl_xor_sync(0xffffffffu, qs, o);
        ks += __shfl_xor_sync(0xffffffffu, ks, o);
    }
    const float qn = fmaxf(sqrtf(qs), 1e-12f);
    const float kn = fmaxf(sqrtf(ks), 1e-12f);

    float2 sc = *(const float2*)(sqk + h * D_ + 2 * p);
    const float iq = (32.0f * 8.0f) / qn;   // s_qk scale 32, sqrt(D)=8 folded in q
    const float ik = 32.0f / kn;

    const float q0 = qr.x * iq * sc.x, q1 = qr.y * iq * sc.y;
    const float k0 = kr.x * ik * sc.x, k1 = kr.y * ik * sc.y;
    const float v0 = v2.x,             v1 = v2.y;

    uint32_t qhi, khi, vhi;
    asm("cvt.rn.bf16x2.f32 %0, %1, %2;" : "=r"(qhi) : "f"(q1), "f"(q0));
    asm("cvt.rn.bf16x2.f32 %0, %1, %2;" : "=r"(khi) : "f"(k1), "f"(k0));
    asm("cvt.rn.bf16x2.f32 %0, %1, %2;" : "=r"(vhi) : "f"(v1), "f"(v0));
    const float qr0 = q0 - __uint_as_float(qhi << 16);
    const float qr1 = q1 - __uint_as_float(qhi & 0xffff0000u);
    const float kr0 = k0 - __uint_as_float(khi << 16);
    const float kr1 = k1 - __uint_as_float(khi & 0xffff0000u);
    const float vr0 = v0 - __uint_as_float(vhi << 16);
    const float vr1 = v1 - __uint_as_float(vhi & 0xffff0000u);
    uint32_t qlo, klo, vlo;
    asm("cvt.rn.bf16x2.f32 %0, %1, %2;" : "=r"(qlo) : "f"(qr1), "f"(qr0));
    asm("cvt.rn.bf16x2.f32 %0, %1, %2;" : "=r"(klo) : "f"(kr1), "f"(kr0));
    asm("cvt.rn.bf16x2.f32 %0, %1, %2;" : "=r"(vlo) : "f"(vr1), "f"(vr0));

    const size_t dst = (((size_t)(b * H_ + h)) * T_ + t) * D_ + 2 * p;
    *(uint32_t*)(Qp + dst)         = qhi;
    *(uint32_t*)(Qp + AELEM + dst) = qlo;
    *(uint32_t*)(Kp + dst)         = khi;
    *(uint32_t*)(Kp + AELEM + dst) = klo;
    *(uint32_t*)(Vp + dst)         = vhi;
    *(uint32_t*)(Vp + AELEM + dst) = vlo;
}

// ==========================================================================
// Flash attention (R13-validated structure, 64-row q-tiles) + fused output
// split: epilogue emits att as bf16 hi/lo planes directly (Wo GEMM input).
//  warps 0-3: S = Q.K^T (HMMA bf16x3, Q frags register-resident) + softmax,
//             P emitted as bf16 hi/lo planes.
//  warps 4-7: O += P.V (HMMA bf16x3, V B-frags via ldmatrix.trans).
//  K/V hi/lo double-buffered via cp.async.
// ==========================================================================
constexpr int KSTR  = 144;                 // smem row stride bytes (72 bf16)
constexpr int KPL   = 64 * KSTR;           // 9216 B per plane
constexpr int AT_K0 = 0;                   // K: 2 buf x 2 planes = 36864
constexpr int AT_V0 = 4 * KPL;             // V: 2 buf x 2 planes = 36864
constexpr int AT_P0 = 8 * KPL;             // P: 2 planes = 18432 (Q staged here)
constexpr int AT_AL = 10 * KPL;            // alphaF: 64 f = 256
constexpr int AT_LI = AT_AL + 256;         // linv: 64 f = 256
constexpr int AT_SM = AT_LI + 256;         // 92672 bytes

__global__ void __launch_bounds__(256, 2) attn_kernel(
    const __nv_bfloat16* __restrict__ Qp,   // hi; lo at +AELEM
    const __nv_bfloat16* __restrict__ Kp,
    const __nv_bfloat16* __restrict__ Vp,
    __nv_bfloat16* __restrict__ Yh)         // att bf16 hi; lo at +AELEM, [BT][C]
{
    extern __shared__ char smc[];
    const uint32_t sb = smem_u32(smc);
    float* alphaF = (float*)(smc + AT_AL);
    float* linv   = (float*)(smc + AT_LI);

    const int tid = threadIdx.x;
    const int wid = tid >> 5, lane = tid & 31;

    const int bh = blockIdx.y;
    const int qt = blockIdx.x;

    const __nv_bfloat16* Qgh = Qp + ((size_t)bh * T_ + qt * 64) * D_;
    const __nv_bfloat16* Qgl = Qgh + AELEM;
    const __nv_bfloat16* Kgh = Kp + (size_t)bh * T_ * D_;
    const __nv_bfloat16* Kgl = Kgh + AELEM;
    const __nv_bfloat16* Vgh = Vp + (size_t)bh * T_ * D_;
    const __nv_bfloat16* Vgl = Vgh + AELEM;

    // prefetch: K hi/lo + V hi/lo, 2 chunks per plane per thread
    auto issue = [&](int kt) {
        const int bsel = kt & 1;
        const __nv_bfloat16* kh = Kgh + (size_t)kt * 64 * D_;
        const __nv_bfloat16* kl = Kgl + (size_t)kt * 64 * D_;
        const __nv_bfloat16* vh = Vgh + (size_t)kt * 64 * D_;
        const __nv_bfloat16* vl = Vgl + (size_t)kt * 64 * D_;
        const uint32_t kd = sb + AT_K0 + bsel * 2 * KPL;
        const uint32_t vd = sb + AT_V0 + bsel * 2 * KPL;
#pragma unroll
        for (int t = 0; t < 2; t++) {
            const int c = tid + t * 256;
            const int row = c >> 3, o = c & 7;
            const uint32_t off = row * KSTR + o * 16;
            CPA16(kd + off,       kh + row * 64 + o * 8);
            CPA16(kd + KPL + off, kl + row * 64 + o * 8);
            CPA16(vd + off,       vh + row * 64 + o * 8);
            CPA16(vd + KPL + off, vl + row * 64 + o * 8);
        }
        CPA_COMMIT();
    };

    issue(0);

    // stage Q hi/lo into smem (aliased over P region), load frags once
    {
        char* qstg = smc + AT_P0;
#pragma unroll
        for (int t = 0; t < 2; t++) {
            const int c = tid + t * 256;
            const int row = c >> 3, o = c & 7;
            *(uint4*)(qstg + row * KSTR + o * 16) =
                *(const uint4*)(Qgh + row * 64 + o * 8);
            *(uint4*)(qstg + KPL + row * KSTR + o * 16) =
                *(const uint4*)(Qgl + row * 64 + o * 8);
        }
    }
    __syncthreads();

    uint32_t qh[4][4], ql[4][4];
    if (wid < 4) {
        const uint32_t aaddr = sb + AT_P0
            + (16 * wid + (lane & 15)) * KSTR + (lane >> 4) * 16;
#pragma unroll
        for (int k16 = 0; k16 < 4; k16++) {
            LDM_X4(qh[k16][0], qh[k16][1], qh[k16][2], qh[k16][3], aaddr + k16 * 32);
            LDM_X4(ql[k16][0], ql[k16][1], ql[k16][2], ql[k16][3],
                   aaddr + KPL + k16 * 32);
        }
    }

    // S-warp softmax state
    float m0r = -3.0e38f, m1r = -3.0e38f, l0r = 0.0f, l1r = 0.0f;
    // PV-warp accumulators: m16 x d64 -> 8 n-frags x 4 f32
    float acc[8][4];
#pragma unroll
    for (int n = 0; n < 8; n++)
#pragma unroll
        for (int c = 0; c < 4; c++) acc[n][c] = 0.0f;

    // K b-frag (non-trans, validated): lane>>4 -> +8 n-rows, lane>>3 -> +16B k.
    const uint32_t bBase = ((lane & 7) + ((lane >> 4) & 1) * 8) * KSTR
                         + ((lane >> 3) & 1) * 16;
    const int r0 = 16 * wid + (lane >> 2);               // S rows (warps 0-3)
    const int r1 = r0 + 8;
    const int pw   = wid - 4;                            // PV warp 0..3
    const int mrow = 16 * pw + (lane >> 2);              // PV rows
    // V b-frag (trans): lane>>3 -> +8 k-rows, lane>>4 -> +16B d.
    const uint32_t vBase = ((lane & 7) + ((lane >> 3) & 1) * 8) * KSTR
                         + ((lane >> 4) & 1) * 16;
    // P a-frag base (non-trans)
    const uint32_t pBase = sb + AT_P0 + (16 * pw + (lane & 15)) * KSTR
                         + (lane >> 4) * 16;

    for (int kt = 0; kt < T_ / 64; kt++) {
        const int buf = kt & 1;
        asm volatile("cp.async.wait_group 0;" ::: "memory");
        __syncthreads();                         // tile kt ready; PV(kt-1) done
        if (kt + 1 < T_ / 64) issue(kt + 1);

        if (wid < 4) {
            // ---- S = Q.K^T : m16n64, 3-term bf16 ----
            float sacc[8][4];
#pragma unroll
            for (int n = 0; n < 8; n++)
#pragma unroll
                for (int c = 0; c < 4; c++) sacc[n][c] = 0.0f;

            const uint32_t kbase = sb + AT_K0 + buf * 2 * KPL + bBase;
#pragma unroll
            for (int k16 = 0; k16 < 4; k16++) {
                uint32_t kb[8][2];
#pragma unroll
                for (int nt = 0; nt < 4; nt++) {
                    uint32_t a0, a1, a2, a3;
                    LDM_X4(a0, a1, a2, a3, kbase + nt * (16 * KSTR) + k16 * 32);
                    kb[2 * nt][0] = a0; kb[2 * nt][1] = a1;
                    kb[2 * nt + 1][0] = a2; kb[2 * nt + 1][1] = a3;
                }
#pragma unroll
                for (int n = 0; n < 8; n++) MMA16816(sacc[n], qh[k16], kb[n]);
#pragma unroll
                for (int n = 0; n < 8; n++) MMA16816(sacc[n], ql[k16], kb[n]);
#pragma unroll
                for (int nt = 0; nt < 4; nt++) {
                    uint32_t a0, a1, a2, a3;
                    LDM_X4(a0, a1, a2, a3,
                           kbase + KPL + nt * (16 * KSTR) + k16 * 32);
                    kb[2 * nt][0] = a0; kb[2 * nt][1] = a1;
                    kb[2 * nt + 1][0] = a2; kb[2 * nt + 1][1] = a3;
                }
#pragma unroll
                for (int n = 0; n < 8; n++) MMA16816(sacc[n], qh[k16], kb[n]);
            }

            // ---- softmax on fragments ----
            float mt0 = sacc[0][0], mt1 = sacc[0][2];
#pragma unroll
            for (int n = 0; n < 8; n++) {
                mt0 = fmaxf(mt0, fmaxf(sacc[n][0], sacc[n][1]));
                mt1 = fmaxf(mt1, fmaxf(sacc[n][2], sacc[n][3]));
            }
            mt0 = fmaxf(mt0, __shfl_xor_sync(0xffffffffu, mt0, 1));
            mt0 = fmaxf(mt0, __shfl_xor_sync(0xffffffffu, mt0, 2));
            mt1 = fmaxf(mt1, __shfl_xor_sync(0xffffffffu, mt1, 1));
            mt1 = fmaxf(mt1, __shfl_xor_sync(0xffffffffu, mt1, 2));
            const float mn0 = fmaxf(m0r, mt0), mn1 = fmaxf(m1r, mt1);
            const float al0 = __expf(m0r - mn0), al1 = __expf(m1r - mn1);

            float ps0 = 0.0f, ps1 = 0.0f;
            const int cb = (lane & 3) * 2;
#pragma unroll
            for (int n = 0; n < 8; n++) {
                const int col = n * 8 + cb;
                const float p00 = __expf(sacc[n][0] - mn0);
                const float p01 = __expf(sacc[n][1] - mn0);
                const float p10 = __expf(sacc[n][2] - mn1);
                const float p11 = __expf(sacc[n][3] - mn1);
                ps0 += p00 + p01; ps1 += p10 + p11;
                // split to bf16 hi/lo and store packed pairs
                uint32_t h0, h1;
                asm("cvt.rn.bf16x2.f32 %0, %1, %2;" : "=r"(h0) : "f"(p01), "f"(p00));
                asm("cvt.rn.bf16x2.f32 %0, %1, %2;" : "=r"(h1) : "f"(p11), "f"(p10));
                const float q00 = p00 - __uint_as_float(h0 << 16);
                const float q01 = p01 - __uint_as_float(h0 & 0xffff0000u);
                const float q10 = p10 - __uint_as_float(h1 << 16);
                const float q11 = p11 - __uint_as_float(h1 & 0xffff0000u);
                uint32_t l0, l1;
                asm("cvt.rn.bf16x2.f32 %0, %1, %2;" : "=r"(l0) : "f"(q01), "f"(q00));
                asm("cvt.rn.bf16x2.f32 %0, %1, %2;" : "=r"(l1) : "f"(q11), "f"(q10));
                char* pp = smc + AT_P0;
                *(uint32_t*)(pp + r0 * KSTR + col * 2)       = h0;
                *(uint32_t*)(pp + r1 * KSTR + col * 2)       = h1;
                *(uint32_t*)(pp + KPL + r0 * KSTR + col * 2) = l0;
                *(uint32_t*)(pp + KPL + r1 * KSTR + col * 2) = l1;
            }
            ps0 += __shfl_xor_sync(0xffffffffu, ps0, 1);
            ps0 += __shfl_xor_sync(0xffffffffu, ps0, 2);
            ps1 += __shfl_xor_sync(0xffffffffu, ps1, 1);
            ps1 += __shfl_xor_sync(0xffffffffu, ps1, 2);
            l0r = l0r * al0 + ps0;  m0r = mn0;
            l1r = l1r * al1 + ps1;  m1r = mn1;
            if ((lane & 3) == 0) {
                alphaF[r0] = al0;
                alphaF[r1] = al1;
                if (kt == T_ / 64 - 1) {
                    linv[r0] = 1.0f / l0r;
                    linv[r1] = 1.0f / l1r;
                }
            }
        }
        __syncthreads();                         // P, alphaF ready

        if (wid >= 4) {
            // ---- rescale ----
            const float a0 = alphaF[mrow];
            const float a1 = alphaF[mrow + 8];
#pragma unroll
            for (int n = 0; n < 8; n++) {
                acc[n][0] *= a0; acc[n][1] *= a0;
                acc[n][2] *= a1; acc[n][3] *= a1;
            }
            // ---- O += P.V (3 terms) ----
            const uint32_t vb = sb + AT_V0 + buf * 2 * KPL + vBase;
#pragma unroll
            for (int k16 = 0; k16 < 4; k16++) {
                uint32_t ph[4], pl[4];
                LDM_X4(ph[0], ph[1], ph[2], ph[3], pBase + k16 * 32);
                LDM_X4(pl[0], pl[1], pl[2], pl[3], pBase + KPL + k16 * 32);
#pragma unroll
                for (int d16 = 0; d16 < 4; d16++) {
                    uint32_t vh[4], vl[4];
                    LDM_X4_T(vh[0], vh[1], vh[2], vh[3],
                             vb + k16 * (16 * KSTR) + d16 * 32);
                    LDM_X4_T(vl[0], vl[1], vl[2], vl[3],
                             vb + KPL + k16 * (16 * KSTR) + d16 * 32);
                    uint32_t bvh0[2] = { vh[0], vh[1] }, bvh1[2] = { vh[2], vh[3] };
                    uint32_t bvl0[2] = { vl[0], vl[1] }, bvl1[2] = { vl[2], vl[3] };
                    MMA16816(acc[2 * d16],     ph, bvh0);
                    MMA16816(acc[2 * d16 + 1], ph, bvh1);
                    MMA16816(acc[2 * d16],     ph, bvl0);
                    MMA16816(acc[2 * d16 + 1], ph, bvl1);
                    MMA16816(acc[2 * d16],     pl, bvh0);
                    MMA16816(acc[2 * d16 + 1], pl, bvh1);
                }
            }
        }
    }

    // ---- epilogue (warps 4-7): O * linv -> bf16 hi/lo planes in [BT][C] ----
    if (wid >= 4) {
        const int b = bh >> 4, h = bh & 15;
        const float li0 = linv[mrow];
        const float li1 = linv[mrow + 8];
        const size_t row0 = (size_t)b * T_ + qt * 64 + mrow;
        __nv_bfloat16* d0 = Yh + row0 * C_ + h * D_;
        __nv_bfloat16* d1 = d0 + (size_t)8 * C_;
        const int cb = (lane & 3) * 2;
#pragma unroll
        for (int n = 0; n < 8; n++) {
            const int col = n * 8 + cb;
            const float y00 = acc[n][0] * li0, y01 = acc[n][1] * li0;
            const float y10 = acc[n][2] * li1, y11 = acc[n][3] * li1;
            uint32_t h0, h1;
            asm("cvt.rn.bf16x2.f32 %0, %1, %2;" : "=r"(h0) : "f"(y01), "f"(y00));
            asm("cvt.rn.bf16x2.f32 %0, %1, %2;" : "=r"(h1) : "f"(y11), "f"(y10));
            const float z00 = y00 - __uint_as_float(h0 << 16);
            const float z01 = y01 - __uint_as_float(h0 & 0xffff0000u);
            const float z10 = y10 - __uint_as_float(h1 << 16);
            const float z11 = y11 - __uint_as_float(h1 & 0xffff0000u);
            uint32_t l0, l1;
            asm("cvt.rn.bf16x2.f32 %0, %1, %2;" : "=r"(l0) : "f"(z01), "f"(z00));
            asm("cvt.rn.bf16x2.f32 %0, %1, %2;" : "=r"(l1) : "f"(z11), "f"(z10));
            *(uint32_t*)(d0 + col)         = h0;
            *(uint32_t*)(d0 + AELEM + col) = l0;
            *(uint32_t*)(d1 + col)         = h1;
            *(uint32_t*)(d1 + AELEM + col) = l1;
        }
    }
}

// ==========================================================================
extern "C" void kernel_launch(void* const* d_in, const int* in_sizes, int n_in,
                              void* d_out, int out_size)
{
    const float* x   = (const float*)d_in[0];
    const float* Wq  = (const float*)d_in[1];
    const float* Wk  = (const float*)d_in[2];
    const float* Wv  = (const float*)d_in[3];
    const float* Wo  = (const float*)d_in[4];
    const float* sqk = (const float*)d_in[5];
    float* out = (float*)d_out;

    static float *q = nullptr, *k, *v, *qn, *kn, *vn;
    static __nv_bfloat16 *xs, *ws, *as;
    static bool init_done = false;
    if (!init_done) {
        cudaGetSymbolAddress((void**)&q,   g_q);
        cudaGetSymbolAddress((void**)&k,   g_k);
        cudaGetSymbolAddress((void**)&v,   g_v);
        cudaGetSymbolAddress((void**)&qn,  g_qn);
        cudaGetSymbolAddress((void**)&kn,  g_kn);
        cudaGetSymbolAddress((void**)&vn,  g_vn);
        cudaGetSymbolAddress((void**)&xs,  g_xs);
        cudaGetSymbolAddress((void**)&ws,  g_ws);
        cudaGetSymbolAddress((void**)&as,  g_as);
        cudaFuncSetAttribute(attn_kernel,
                             cudaFuncAttributeMaxDynamicSharedMemorySize, AT_SM);
        cudaFuncSetAttribute(gemm_hmma_kernel,
                             cudaFuncAttributeMaxDynamicSharedMemorySize, GSMEM);
        init_done = true;
    }

    // split x and the 4 weight matrices to bf16 hi/lo planes
    split_kernel<<<AELEM / 4 / 256, 256>>>((const float4*)x, (uint2*)xs,
                                           (uint2*)(xs + AELEM));
    split_w_kernel<<<dim3(WELEM / 4 / 256, 1, 4), 256>>>(Wq, Wk, Wv, Wo, ws);

    // QKV projections on HMMA (bf16x3)
    gemm_hmma_kernel<<<dim3(8, 32, 3), 256, GSMEM>>>(xs, ws, q, k, v);

    // RoPE + norm; Q/K/V emitted as bf16 hi/lo planes
    rope_norm_kernel<<<(BT_ * H_) / 8, 256>>>(
        q, k, v, sqk, (__nv_bfloat16*)qn, (__nv_bfloat16*)kn, (__nv_bfloat16*)vn);

    // Flash attention (S and PV on HMMA bf16x3, 64-row q-tiles,
    // epilogue emits att directly as bf16 hi/lo planes)
    attn_kernel<<<dim3(T_ / 64, BH_), 256, AT_SM>>>(
        (const __nv_bfloat16*)qn, (const __nv_bfloat16*)kn,
        (const __nv_bfloat16*)vn, as);

    // Wo projection on HMMA (att split fused into attention epilogue)
    gemm_hmma_kernel<<<dim3(8, 32, 1), 256, GSMEM>>>(as, ws + (size_t)3 * 2 * WELEM,
                                                     out, out, out);
}

// round 17
// speedup vs baseline: 1.3575x; 1.0749x over previous
#include <cuda_runtime.h>
#include <cuda_bf16.h>
#include <cstdint>

typedef unsigned long long ull;

constexpr int B_ = 2, T_ = 2048, C_ = 1024, H_ = 16, D_ = 64;
constexpr int BT_ = B_ * T_;   // 4096
constexpr int BH_ = B_ * H_;   // 32
constexpr int AELEM = BT_ * C_;      // 4194304
constexpr int WELEM = C_ * C_;       // 1048576

// ---------------- scratch (static device arrays; no allocation allowed) ----
__device__ float g_q [BT_ * C_];
__device__ float g_k [BT_ * C_];
__device__ float g_v [BT_ * C_];
__device__ float g_qn[BT_ * C_];   // reused: Q bf16 hi|lo planes [BH][T][D]
__device__ float g_kn[BT_ * C_];   // reused: K bf16 hi|lo planes [BH][T][D]
__device__ float g_vn[BT_ * C_];   // reused: V bf16 hi|lo planes [BH][T][D]

__device__ __nv_bfloat16 g_xs [2 * AELEM];      // x  split: hi | lo
__device__ __nv_bfloat16 g_ws [4 * 2 * WELEM];  // Wq,Wk,Wv,Wo: per-matrix hi | lo
__device__ __nv_bfloat16 g_as [2 * AELEM];      // att bf16: hi | lo (from attn epi)

// ---------------- helpers --------------------------------------------------
__device__ __forceinline__ uint32_t smem_u32(const void* p) {
    uint32_t a;
    asm("{ .reg .u64 t; cvta.to.shared.u64 t, %1; cvt.u32.u64 %0, t; }" : "=r"(a) : "l"(p));
    return a;
}

// ==========================================================================
// Split fp32 -> bf16 (hi) + bf16(residual) (lo).  4 elements / thread.
// ==========================================================================
__global__ void __launch_bounds__(256) split_kernel(
    const float4* __restrict__ in, uint2* __restrict__ hi, uint2* __restrict__ lo)
{
    const int i = blockIdx.x * blockDim.x + threadIdx.x;
    float4 f = in[i];
    uint32_t h0, h1;
    asm("cvt.rn.bf16x2.f32 %0, %1, %2;" : "=r"(h0) : "f"(f.y), "f"(f.x));
    asm("cvt.rn.bf16x2.f32 %0, %1, %2;" : "=r"(h1) : "f"(f.w), "f"(f.z));
    float r0 = f.x - __uint_as_float(h0 << 16);
    float r1 = f.y - __uint_as_float(h0 & 0xffff0000u);
    float r2 = f.z - __uint_as_float(h1 << 16);
    float r3 = f.w - __uint_as_float(h1 & 0xffff0000u);
    uint32_t l0, l1;
    asm("cvt.rn.bf16x2.f32 %0, %1, %2;" : "=r"(l0) : "f"(r1), "f"(r0));
    asm("cvt.rn.bf16x2.f32 %0, %1, %2;" : "=r"(l1) : "f"(r3), "f"(r2));
    hi[i] = make_uint2(h0, h1);
    lo[i] = make_uint2(l0, l1);
}

// W splitter: grid.z selects which W; outputs into g_ws + z*2*WELEM.
__global__ void __launch_bounds__(256) split_w_kernel(
    const float* __restrict__ W0, const float* __restrict__ W1,
    const float* __restrict__ W2, const float* __restrict__ W3,
    __nv_bfloat16* __restrict__ ws)
{
    const float* W = (blockIdx.z == 0) ? W0 : (blockIdx.z == 1) ? W1
                   : (blockIdx.z == 2) ? W2 : W3;
    const int i = blockIdx.x * blockDim.x + threadIdx.x;
    float4 f = ((const float4*)W)[i];
    uint32_t h0, h1;
    asm("cvt.rn.bf16x2.f32 %0, %1, %2;" : "=r"(h0) : "f"(f.y), "f"(f.x));
    asm("cvt.rn.bf16x2.f32 %0, %1, %2;" : "=r"(h1) : "f"(f.w), "f"(f.z));
    float r0 = f.x - __uint_as_float(h0 << 16);
    float r1 = f.y - __uint_as_float(h0 & 0xffff0000u);
    float r2 = f.z - __uint_as_float(h1 << 16);
    float r3 = f.w - __uint_as_float(h1 & 0xffff0000u);
    uint32_t l0, l1;
    asm("cvt.rn.bf16x2.f32 %0, %1, %2;" : "=r"(l0) : "f"(r1), "f"(r0));
    asm("cvt.rn.bf16x2.f32 %0, %1, %2;" : "=r"(l1) : "f"(r3), "f"(r2));
    uint2* hi = (uint2*)(ws + (size_t)blockIdx.z * 2 * WELEM);
    uint2* lo = (uint2*)(ws + (size_t)blockIdx.z * 2 * WELEM + WELEM);
    hi[i] = make_uint2(h0, h1);
    lo[i] = make_uint2(l0, l1);
}

// ==========================================================================
// HMMA building blocks (validated R10-R15)
// ==========================================================================
#define CPA16(dst, src) \
    asm volatile("cp.async.cg.shared.global [%0], [%1], 16;" :: "r"(dst), "l"(src))
#define CPA_COMMIT() asm volatile("cp.async.commit_group;" ::: "memory")

#define LDM_X4(r0, r1, r2, r3, a) \
    asm volatile("ldmatrix.sync.aligned.m8n8.x4.shared.b16 {%0,%1,%2,%3}, [%4];" \
                 : "=r"(r0), "=r"(r1), "=r"(r2), "=r"(r3) : "r"(a))

#define LDM_X4_T(r0, r1, r2, r3, a) \
    asm volatile("ldmatrix.sync.aligned.m8n8.x4.trans.shared.b16 {%0,%1,%2,%3}, [%4];" \
                 : "=r"(r0), "=r"(r1), "=r"(r2), "=r"(r3) : "r"(a))

#define MMA16816(c, a, b) \
    asm volatile("mma.sync.aligned.m16n8k16.row.col.f32.bf16.bf16.f32 " \
                 "{%0,%1,%2,%3}, {%4,%5,%6,%7}, {%8,%9}, {%0,%1,%2,%3};" \
                 : "+f"((c)[0]), "+f"((c)[1]), "+f"((c)[2]), "+f"((c)[3]) \
                 : "r"((a)[0]), "r"((a)[1]), "r"((a)[2]), "r"((a)[3]), \
                   "r"((b)[0]), "r"((b)[1]))

// ==========================================================================
// HMMA GEMM: O[m,n] = sum_k A[m,k] * W[n,k], bf16x3.
// R16: term-major mma ordering -> accumulator reuse distance 16 (was 1).
// ==========================================================================
constexpr int GST   = 40;                    // smem row stride (bf16)
constexpr int PLANE = 128 * GST * 2;         // 10240 B
constexpr int GBUF  = 4 * PLANE;             // 40960 B
constexpr int GSMEM = 2 * GBUF;              // 81920 B

__global__ void __launch_bounds__(256) gemm_hmma_kernel(
    const __nv_bfloat16* __restrict__ As,
    const __nv_bfloat16* __restrict__ Ws,
    float* __restrict__ O0, float* __restrict__ O1, float* __restrict__ O2)
{
    extern __shared__ char smem[];
    const uint32_t sb = smem_u32(smem);
    const int tid  = threadIdx.x;
    const int wid  = tid >> 5, lane = tid & 31;
    const int m0   = blockIdx.y * 128;
    const int n0   = blockIdx.x * 128;
    const int wm   = (wid & 1) * 64;
    const int wn   = (wid >> 1) * 32;

    float* O = (blockIdx.z == 0) ? O0 : ((blockIdx.z == 1) ? O1 : O2);
    const __nv_bfloat16* Ah = As;
    const __nv_bfloat16* Al = As + AELEM;
    const __nv_bfloat16* Bh = Ws + (size_t)blockIdx.z * 2 * WELEM;
    const __nv_bfloat16* Bl = Bh + WELEM;

    const int lrow = tid >> 2;
    const int lk8  = (tid & 3) * 8;

    float acc[4][4][4];
#pragma unroll
    for (int i = 0; i < 4; i++)
#pragma unroll
        for (int j = 0; j < 4; j++)
#pragma unroll
            for (int c = 0; c < 4; c++) acc[i][j][c] = 0.0f;

    const uint32_t aBase = (uint32_t)((wm + (lane & 15)) * (GST * 2) + (lane >> 4) * 16);
    const uint32_t bBase = (uint32_t)((wn + (lane & 7) + ((lane >> 4) & 1) * 8) * (GST * 2)
                                      + ((lane >> 3) & 1) * 16);

    auto issue_stage = [&](int kt, int buf) {
        const int k0 = kt * 32;
        const uint32_t dbase = sb + buf * GBUF;
#pragma unroll
        for (int h = 0; h < 2; h++) {
            const int row = lrow + h * 64;
            const uint32_t doff = (uint32_t)(row * (GST * 2) + lk8 * 2);
            CPA16(dbase + 0 * PLANE + doff, Ah + (size_t)(m0 + row) * 1024 + k0 + lk8);
            CPA16(dbase + 1 * PLANE + doff, Al + (size_t)(m0 + row) * 1024 + k0 + lk8);
            CPA16(dbase + 2 * PLANE + doff, Bh + (size_t)(n0 + row) * 1024 + k0 + lk8);
            CPA16(dbase + 3 * PLANE + doff, Bl + (size_t)(n0 + row) * 1024 + k0 + lk8);
        }
        CPA_COMMIT();
    };

    issue_stage(0, 0);

    for (int kt = 0; kt < 32; ++kt) {
        const int buf = kt & 1;
        if (kt + 1 < 32) {
            issue_stage(kt + 1, (kt + 1) & 1);
            asm volatile("cp.async.wait_group 1;" ::: "memory");
        } else {
            asm volatile("cp.async.wait_group 0;" ::: "memory");
        }
        __syncthreads();

        const uint32_t bbase = sb + buf * GBUF;
#pragma unroll
        for (int k16 = 0; k16 < 2; ++k16) {
            const uint32_t ko = (uint32_t)(k16 * 32);
            uint32_t ah[4][4], al[4][4];
#pragma unroll
            for (int i = 0; i < 4; i++) {
                LDM_X4(ah[i][0], ah[i][1], ah[i][2], ah[i][3],
                       bbase + 0 * PLANE + aBase + i * (16 * GST * 2) + ko);
                LDM_X4(al[i][0], al[i][1], al[i][2], al[i][3],
                       bbase + 1 * PLANE + aBase + i * (16 * GST * 2) + ko);
            }
            uint32_t bh[4][2], bl[4][2];
#pragma unroll
            for (int j2 = 0; j2 < 2; j2++) {
                uint32_t r0, r1, r2, r3;
                LDM_X4(r0, r1, r2, r3,
                       bbase + 2 * PLANE + bBase + j2 * (16 * GST * 2) + ko);
                bh[2 * j2][0] = r0; bh[2 * j2][1] = r1;
                bh[2 * j2 + 1][0] = r2; bh[2 * j2 + 1][1] = r3;
                LDM_X4(r0, r1, r2, r3,
                       bbase + 3 * PLANE + bBase + j2 * (16 * GST * 2) + ko);
                bl[2 * j2][0] = r0; bl[2 * j2][1] = r1;
                bl[2 * j2 + 1][0] = r2; bl[2 * j2 + 1][1] = r3;
            }
            // term-major: 3 passes of 16 independent mma (reuse distance 16)
#pragma unroll
            for (int i = 0; i < 4; i++)
#pragma unroll
                for (int j = 0; j < 4; j++)
                    MMA16816(acc[i][j], ah[i], bh[j]);
#pragma unroll
            for (int i = 0; i < 4; i++)
#pragma unroll
                for (int j = 0; j < 4; j++)
                    MMA16816(acc[i][j], ah[i], bl[j]);
#pragma unroll
            for (int i = 0; i < 4; i++)
#pragma unroll
                for (int j = 0; j < 4; j++)
                    MMA16816(acc[i][j], al[i], bh[j]);
        }
        __syncthreads();
    }

    const int r0 = lane >> 2, c0 = (lane & 3) * 2;
#pragma unroll
    for (int i = 0; i < 4; i++) {
#pragma unroll
        for (int j = 0; j < 4; j++) {
            float* p = O + (size_t)(m0 + wm + i * 16 + r0) * 1024 + n0 + wn + j * 8 + c0;
            *(float2*)p = make_float2(acc[i][j][0], acc[i][j][1]);
            *(float2*)(p + 8 * 1024) = make_float2(acc[i][j][2], acc[i][j][3]);
        }
    }
}

// ==========================================================================
// RoPE + L2 norm + scale; emits Q, K, V all as bf16 hi/lo planes [BH][T][D].
// ==========================================================================
__global__ void __launch_bounds__(256) rope_norm_kernel(
    const float* __restrict__ tq, const float* __restrict__ tk, const float* __restrict__ tv,
    const float* __restrict__ sqk,
    __nv_bfloat16* __restrict__ Qp,   // hi plane; lo at +AELEM
    __nv_bfloat16* __restrict__ Kp,
    __nv_bfloat16* __restrict__ Vp)
{
    const int gw   = (blockIdx.x * blockDim.x + threadIdx.x) >> 5;
    const int lane = threadIdx.x & 31;
    const int h  = gw & (H_ - 1);
    const int bt = gw >> 4;
    const int t  = bt & (T_ - 1);
    const int b  = bt >> 11;
    const int p  = lane;

    const size_t src = (size_t)bt * C_ + h * D_ + 2 * p;
    float2 q2 = *(const float2*)(tq + src);
    float2 k2 = *(const float2*)(tk + src);
    float2 v2 = *(const float2*)(tv + src);

    const float ex   = -((float)(2 * p) / (float)D_) * 13.287712379549449f;
    const float invf = exp2f(ex);
    float sn, cs;
    sincosf((float)t * invf, &sn, &cs);

    float2 qr, kr;
    qr.x = q2.x * cs - q2.y * sn;  qr.y = q2.y * cs + q2.x * sn;
    kr.x = k2.x * cs - k2.y * sn;  kr.y = k2.y * cs + k2.x * sn;

    float qs = qr.x * qr.x + qr.y * qr.y;
    float ks = kr.x * kr.x + kr.y * kr.y;
#pragma unroll
    for (int o = 16; o > 0; o >>= 1) {
        qs += __shfl_xor_sync(0xffffffffu, qs, o);
        ks += __shfl_xor_sync(0xffffffffu, ks, o);
    }
    const float qn = fmaxf(sqrtf(qs), 1e-12f);
    const float kn = fmaxf(sqrtf(ks), 1e-12f);

    float2 sc = *(const float2*)(sqk + h * D_ + 2 * p);
    const float iq = (32.0f * 8.0f) / qn;   // s_qk scale 32, sqrt(D)=8 folded in q
    const float ik = 32.0f / kn;

    const float q0 = qr.x * iq * sc.x, q1 = qr.y * iq * sc.y;
    const float k0 = kr.x * ik * sc.x, k1 = kr.y * ik * sc.y;
    const float v0 = v2.x,             v1 = v2.y;

    uint32_t qhi, khi, vhi;
    asm("cvt.rn.bf16x2.f32 %0, %1, %2;" : "=r"(qhi) : "f"(q1), "f"(q0));
    asm("cvt.rn.bf16x2.f32 %0, %1, %2;" : "=r"(khi) : "f"(k1), "f"(k0));
    asm("cvt.rn.bf16x2.f32 %0, %1, %2;" : "=r"(vhi) : "f"(v1), "f"(v0));
    const float qr0 = q0 - __uint_as_float(qhi << 16);
    const float qr1 = q1 - __uint_as_float(qhi & 0xffff0000u);
    const float kr0 = k0 - __uint_as_float(khi << 16);
    const float kr1 = k1 - __uint_as_float(khi & 0xffff0000u);
    const float vr0 = v0 - __uint_as_float(vhi << 16);
    const float vr1 = v1 - __uint_as_float(vhi & 0xffff0000u);
    uint32_t qlo, klo, vlo;
    asm("cvt.rn.bf16x2.f32 %0, %1, %2;" : "=r"(qlo) : "f"(qr1), "f"(qr0));
    asm("cvt.rn.bf16x2.f32 %0, %1, %2;" : "=r"(klo) : "f"(kr1), "f"(kr0));
    asm("cvt.rn.bf16x2.f32 %0, %1, %2;" : "=r"(vlo) : "f"(vr1), "f"(vr0));

    const size_t dst = (((size_t)(b * H_ + h)) * T_ + t) * D_ + 2 * p;
    *(uint32_t*)(Qp + dst)         = qhi;
    *(uint32_t*)(Qp + AELEM + dst) = qlo;
    *(uint32_t*)(Kp + dst)         = khi;
    *(uint32_t*)(Kp + AELEM + dst) = klo;
    *(uint32_t*)(Vp + dst)         = vhi;
    *(uint32_t*)(Vp + AELEM + dst) = vlo;
}

// ==========================================================================
// Flash attention (R13/R15-validated, 64-row q-tiles, fused output split).
// R16: PV mma reordered term-major (reuse distance 8, was 1-2).
// ==========================================================================
constexpr int KSTR  = 144;                 // smem row stride bytes (72 bf16)
constexpr int KPL   = 64 * KSTR;           // 9216 B per plane
constexpr int AT_K0 = 0;                   // K: 2 buf x 2 planes = 36864
constexpr int AT_V0 = 4 * KPL;             // V: 2 buf x 2 planes = 36864
constexpr int AT_P0 = 8 * KPL;             // P: 2 planes = 18432 (Q staged here)
constexpr int AT_AL = 10 * KPL;            // alphaF: 64 f = 256
constexpr int AT_LI = AT_AL + 256;         // linv: 64 f = 256
constexpr int AT_SM = AT_LI + 256;         // 92672 bytes

__global__ void __launch_bounds__(256, 2) attn_kernel(
    const __nv_bfloat16* __restrict__ Qp,   // hi; lo at +AELEM
    const __nv_bfloat16* __restrict__ Kp,
    const __nv_bfloat16* __restrict__ Vp,
    __nv_bfloat16* __restrict__ Yh)         // att bf16 hi; lo at +AELEM, [BT][C]
{
    extern __shared__ char smc[];
    const uint32_t sb = smem_u32(smc);
    float* alphaF = (float*)(smc + AT_AL);
    float* linv   = (float*)(smc + AT_LI);

    const int tid = threadIdx.x;
    const int wid = tid >> 5, lane = tid & 31;

    const int bh = blockIdx.y;
    const int qt = blockIdx.x;

    const __nv_bfloat16* Qgh = Qp + ((size_t)bh * T_ + qt * 64) * D_;
    const __nv_bfloat16* Qgl = Qgh + AELEM;
    const __nv_bfloat16* Kgh = Kp + (size_t)bh * T_ * D_;
    const __nv_bfloat16* Kgl = Kgh + AELEM;
    const __nv_bfloat16* Vgh = Vp + (size_t)bh * T_ * D_;
    const __nv_bfloat16* Vgl = Vgh + AELEM;

    // prefetch: K hi/lo + V hi/lo, 2 chunks per plane per thread
    auto issue = [&](int kt) {
        const int bsel = kt & 1;
        const __nv_bfloat16* kh = Kgh + (size_t)kt * 64 * D_;
        const __nv_bfloat16* kl = Kgl + (size_t)kt * 64 * D_;
        const __nv_bfloat16* vh = Vgh + (size_t)kt * 64 * D_;
        const __nv_bfloat16* vl = Vgl + (size_t)kt * 64 * D_;
        const uint32_t kd = sb + AT_K0 + bsel * 2 * KPL;
        const uint32_t vd = sb + AT_V0 + bsel * 2 * KPL;
#pragma unroll
        for (int t = 0; t < 2; t++) {
            const int c = tid + t * 256;
            const int row = c >> 3, o = c & 7;
            const uint32_t off = row * KSTR + o * 16;
            CPA16(kd + off,       kh + row * 64 + o * 8);
            CPA16(kd + KPL + off, kl + row * 64 + o * 8);
            CPA16(vd + off,       vh + row * 64 + o * 8);
            CPA16(vd + KPL + off, vl + row * 64 + o * 8);
        }
        CPA_COMMIT();
    };

    issue(0);

    // stage Q hi/lo into smem (aliased over P region), load frags once
    {
        char* qstg = smc + AT_P0;
#pragma unroll
        for (int t = 0; t < 2; t++) {
            const int c = tid + t * 256;
            const int row = c >> 3, o = c & 7;
            *(uint4*)(qstg + row * KSTR + o * 16) =
                *(const uint4*)(Qgh + row * 64 + o * 8);
            *(uint4*)(qstg + KPL + row * KSTR + o * 16) =
                *(const uint4*)(Qgl + row * 64 + o * 8);
        }
    }
    __syncthreads();

    uint32_t qh[4][4], ql[4][4];
    if (wid < 4) {
        const uint32_t aaddr = sb + AT_P0
            + (16 * wid + (lane & 15)) * KSTR + (lane >> 4) * 16;
#pragma unroll
        for (int k16 = 0; k16 < 4; k16++) {
            LDM_X4(qh[k16][0], qh[k16][1], qh[k16][2], qh[k16][3], aaddr + k16 * 32);
            LDM_X4(ql[k16][0], ql[k16][1], ql[k16][2], ql[k16][3],
                   aaddr + KPL + k16 * 32);
        }
    }

    // S-warp softmax state
    float m0r = -3.0e38f, m1r = -3.0e38f, l0r = 0.0f, l1r = 0.0f;
    // PV-warp accumulators: m16 x d64 -> 8 n-frags x 4 f32
    float acc[8][4];
#pragma unroll
    for (int n = 0; n < 8; n++)
#pragma unroll
        for (int c = 0; c < 4; c++) acc[n][c] = 0.0f;

    // K b-frag (non-trans, validated): lane>>4 -> +8 n-rows, lane>>3 -> +16B k.
    const uint32_t bBase = ((lane & 7) + ((lane >> 4) & 1) * 8) * KSTR
                         + ((lane >> 3) & 1) * 16;
    const int r0 = 16 * wid + (lane >> 2);               // S rows (warps 0-3)
    const int r1 = r0 + 8;
    const int pw   = wid - 4;                            // PV warp 0..3
    const int mrow = 16 * pw + (lane >> 2);              // PV rows
    // V b-frag (trans): lane>>3 -> +8 k-rows, lane>>4 -> +16B d.
    const uint32_t vBase = ((lane & 7) + ((lane >> 3) & 1) * 8) * KSTR
                         + ((lane >> 4) & 1) * 16;
    // P a-frag base (non-trans)
    const uint32_t pBase = sb + AT_P0 + (16 * pw + (lane & 15)) * KSTR
                         + (lane >> 4) * 16;

    for (int kt = 0; kt < T_ / 64; kt++) {
        const int buf = kt & 1;
        asm volatile("cp.async.wait_group 0;" ::: "memory");
        __syncthreads();                         // tile kt ready; PV(kt-1) done
        if (kt + 1 < T_ / 64) issue(kt + 1);

        if (wid < 4) {
            // ---- S = Q.K^T : m16n64, 3-term bf16 ----
            float sacc[8][4];
#pragma unroll
            for (int n = 0; n < 8; n++)
#pragma unroll
                for (int c = 0; c < 4; c++) sacc[n][c] = 0.0f;

            const uint32_t kbase = sb + AT_K0 + buf * 2 * KPL + bBase;
#pragma unroll
            for (int k16 = 0; k16 < 4; k16++) {
                uint32_t kb[8][2];
#pragma unroll
                for (int nt = 0; nt < 4; nt++) {
                    uint32_t a0, a1, a2, a3;
                    LDM_X4(a0, a1, a2, a3, kbase + nt * (16 * KSTR) + k16 * 32);
                    kb[2 * nt][0] = a0; kb[2 * nt][1] = a1;
                    kb[2 * nt + 1][0] = a2; kb[2 * nt + 1][1] = a3;
                }
#pragma unroll
                for (int n = 0; n < 8; n++) MMA16816(sacc[n], qh[k16], kb[n]);
#pragma unroll
                for (int n = 0; n < 8; n++) MMA16816(sacc[n], ql[k16], kb[n]);
#pragma unroll
                for (int nt = 0; nt < 4; nt++) {
                    uint32_t a0, a1, a2, a3;
                    LDM_X4(a0, a1, a2, a3,
                           kbase + KPL + nt * (16 * KSTR) + k16 * 32);
                    kb[2 * nt][0] = a0; kb[2 * nt][1] = a1;
                    kb[2 * nt + 1][0] = a2; kb[2 * nt + 1][1] = a3;
                }
#pragma unroll
                for (int n = 0; n < 8; n++) MMA16816(sacc[n], qh[k16], kb[n]);
            }

            // ---- softmax on fragments ----
            float mt0 = sacc[0][0], mt1 = sacc[0][2];
#pragma unroll
            for (int n = 0; n < 8; n++) {
                mt0 = fmaxf(mt0, fmaxf(sacc[n][0], sacc[n][1]));
                mt1 = fmaxf(mt1, fmaxf(sacc[n][2], sacc[n][3]));
            }
            mt0 = fmaxf(mt0, __shfl_xor_sync(0xffffffffu, mt0, 1));
            mt0 = fmaxf(mt0, __shfl_xor_sync(0xffffffffu, mt0, 2));
            mt1 = fmaxf(mt1, __shfl_xor_sync(0xffffffffu, mt1, 1));
            mt1 = fmaxf(mt1, __shfl_xor_sync(0xffffffffu, mt1, 2));
            const float mn0 = fmaxf(m0r, mt0), mn1 = fmaxf(m1r, mt1);
            const float al0 = __expf(m0r - mn0), al1 = __expf(m1r - mn1);

            float ps0 = 0.0f, ps1 = 0.0f;
            const int cb = (lane & 3) * 2;
#pragma unroll
            for (int n = 0; n < 8; n++) {
                const int col = n * 8 + cb;
                const float p00 = __expf(sacc[n][0] - mn0);
                const float p01 = __expf(sacc[n][1] - mn0);
                const float p10 = __expf(sacc[n][2] - mn1);
                const float p11 = __expf(sacc[n][3] - mn1);
                ps0 += p00 + p01; ps1 += p10 + p11;
                // split to bf16 hi/lo and store packed pairs
                uint32_t h0, h1;
                asm("cvt.rn.bf16x2.f32 %0, %1, %2;" : "=r"(h0) : "f"(p01), "f"(p00));
                asm("cvt.rn.bf16x2.f32 %0, %1, %2;" : "=r"(h1) : "f"(p11), "f"(p10));
                const float q00 = p00 - __uint_as_float(h0 << 16);
                const float q01 = p01 - __uint_as_float(h0 & 0xffff0000u);
                const float q10 = p10 - __uint_as_float(h1 << 16);
                const float q11 = p11 - __uint_as_float(h1 & 0xffff0000u);
                uint32_t l0, l1;
                asm("cvt.rn.bf16x2.f32 %0, %1, %2;" : "=r"(l0) : "f"(q01), "f"(q00));
                asm("cvt.rn.bf16x2.f32 %0, %1, %2;" : "=r"(l1) : "f"(q11), "f"(q10));
                char* pp = smc + AT_P0;
                *(uint32_t*)(pp + r0 * KSTR + col * 2)       = h0;
                *(uint32_t*)(pp + r1 * KSTR + col * 2)       = h1;
                *(uint32_t*)(pp + KPL + r0 * KSTR + col * 2) = l0;
                *(uint32_t*)(pp + KPL + r1 * KSTR + col * 2) = l1;
            }
            ps0 += __shfl_xor_sync(0xffffffffu, ps0, 1);
            ps0 += __shfl_xor_sync(0xffffffffu, ps0, 2);
            ps1 += __shfl_xor_sync(0xffffffffu, ps1, 1);
            ps1 += __shfl_xor_sync(0xffffffffu, ps1, 2);
            l0r = l0r * al0 + ps0;  m0r = mn0;
            l1r = l1r * al1 + ps1;  m1r = mn1;
            if ((lane & 3) == 0) {
                alphaF[r0] = al0;
                alphaF[r1] = al1;
                if (kt == T_ / 64 - 1) {
                    linv[r0] = 1.0f / l0r;
                    linv[r1] = 1.0f / l1r;
                }
            }
        }
        __syncthreads();                         // P, alphaF ready

        if (wid >= 4) {
            // ---- rescale ----
            const float a0 = alphaF[mrow];
            const float a1 = alphaF[mrow + 8];
#pragma unroll
            for (int n = 0; n < 8; n++) {
                acc[n][0] *= a0; acc[n][1] *= a0;
                acc[n][2] *= a1; acc[n][3] *= a1;
            }
            // ---- O += P.V (3 terms, term-major: reuse distance 8) ----
            const uint32_t vb = sb + AT_V0 + buf * 2 * KPL + vBase;
#pragma unroll
            for (int k16 = 0; k16 < 4; k16++) {
                uint32_t ph[4], pl[4];
                LDM_X4(ph[0], ph[1], ph[2], ph[3], pBase + k16 * 32);
                LDM_X4(pl[0], pl[1], pl[2], pl[3], pBase + KPL + k16 * 32);
                uint32_t vh[4][4], vl[4][4];
#pragma unroll
                for (int d16 = 0; d16 < 4; d16++) {
                    LDM_X4_T(vh[d16][0], vh[d16][1], vh[d16][2], vh[d16][3],
                             vb + k16 * (16 * KSTR) + d16 * 32);
                    LDM_X4_T(vl[d16][0], vl[d16][1], vl[d16][2], vl[d16][3],
                             vb + KPL + k16 * (16 * KSTR) + d16 * 32);
                }
                // pass 1: Ph * Vh  (8 independent mma)
#pragma unroll
                for (int d16 = 0; d16 < 4; d16++) {
                    uint32_t b0[2] = { vh[d16][0], vh[d16][1] };
                    uint32_t b1[2] = { vh[d16][2], vh[d16][3] };
                    MMA16816(acc[2 * d16],     ph, b0);
                    MMA16816(acc[2 * d16 + 1], ph, b1);
                }
                // pass 2: Ph * Vl
#pragma unroll
                for (int d16 = 0; d16 < 4; d16++) {
                    uint32_t b0[2] = { vl[d16][0], vl[d16][1] };
                    uint32_t b1[2] = { vl[d16][2], vl[d16][3] };
                    MMA16816(acc[2 * d16],     ph, b0);
                    MMA16816(acc[2 * d16 + 1], ph, b1);
                }
                // pass 3: Pl * Vh
#pragma unroll
                for (int d16 = 0; d16 < 4; d16++) {
                    uint32_t b0[2] = { vh[d16][0], vh[d16][1] };
                    uint32_t b1[2] = { vh[d16][2], vh[d16][3] };
                    MMA16816(acc[2 * d16],     pl, b0);
                    MMA16816(acc[2 * d16 + 1], pl, b1);
                }
            }
        }
    }

    // ---- epilogue (warps 4-7): O * linv -> bf16 hi/lo planes in [BT][C] ----
    if (wid >= 4) {
        const int b = bh >> 4, h = bh & 15;
        const float li0 = linv[mrow];
        const float li1 = linv[mrow + 8];
        const size_t row0 = (size_t)b * T_ + qt * 64 + mrow;
        __nv_bfloat16* d0 = Yh + row0 * C_ + h * D_;
        __nv_bfloat16* d1 = d0 + (size_t)8 * C_;
        const int cb = (lane & 3) * 2;
#pragma unroll
        for (int n = 0; n < 8; n++) {
            const int col = n * 8 + cb;
            const float y00 = acc[n][0] * li0, y01 = acc[n][1] * li0;
            const float y10 = acc[n][2] * li1, y11 = acc[n][3] * li1;
            uint32_t h0, h1;
            asm("cvt.rn.bf16x2.f32 %0, %1, %2;" : "=r"(h0) : "f"(y01), "f"(y00));
            asm("cvt.rn.bf16x2.f32 %0, %1, %2;" : "=r"(h1) : "f"(y11), "f"(y10));
            const float z00 = y00 - __uint_as_float(h0 << 16);
            const float z01 = y01 - __uint_as_float(h0 & 0xffff0000u);
            const float z10 = y10 - __uint_as_float(h1 << 16);
            const float z11 = y11 - __uint_as_float(h1 & 0xffff0000u);
            uint32_t l0, l1;
            asm("cvt.rn.bf16x2.f32 %0, %1, %2;" : "=r"(l0) : "f"(z01), "f"(z00));
            asm("cvt.rn.bf16x2.f32 %0, %1, %2;" : "=r"(l1) : "f"(z11), "f"(z10));
            *(uint32_t*)(d0 + col)         = h0;
            *(uint32_t*)(d0 + AELEM + col) = l0;
            *(uint32_t*)(d1 + col)         = h1;
            *(uint32_t*)(d1 + AELEM + col) = l1;
        }
    }
}

// ==========================================================================
extern "C" void kernel_launch(void* const* d_in, const int* in_sizes, int n_in,
                              void* d_out, int out_size)
{
    const float* x   = (const float*)d_in[0];
    const float* Wq  = (const float*)d_in[1];
    const float* Wk  = (const float*)d_in[2];
    const float* Wv  = (const float*)d_in[3];
    const float* Wo  = (const float*)d_in[4];
    const float* sqk = (const float*)d_in[5];
    float* out = (float*)d_out;

    static float *q = nullptr, *k, *v, *qn, *kn, *vn;
    static __nv_bfloat16 *xs, *ws, *as;
    static bool init_done = false;
    if (!init_done) {
        cudaGetSymbolAddress((void**)&q,   g_q);
        cudaGetSymbolAddress((void**)&k,   g_k);
        cudaGetSymbolAddress((void**)&v,   g_v);
        cudaGetSymbolAddress((void**)&qn,  g_qn);
        cudaGetSymbolAddress((void**)&kn,  g_kn);
        cudaGetSymbolAddress((void**)&vn,  g_vn);
        cudaGetSymbolAddress((void**)&xs,  g_xs);
        cudaGetSymbolAddress((void**)&ws,  g_ws);
        cudaGetSymbolAddress((void**)&as,  g_as);
        cudaFuncSetAttribute(attn_kernel,
                             cudaFuncAttributeMaxDynamicSharedMemorySize, AT_SM);
        cudaFuncSetAttribute(gemm_hmma_kernel,
                             cudaFuncAttributeMaxDynamicSharedMemorySize, GSMEM);
        init_done = true;
    }

    // split x and the 4 weight matrices to bf16 hi/lo planes
    split_kernel<<<AELEM / 4 / 256, 256>>>((const float4*)x, (uint2*)xs,
                                           (uint2*)(xs + AELEM));
    split_w_kernel<<<dim3(WELEM / 4 / 256, 1, 4), 256>>>(Wq, Wk, Wv, Wo, ws);

    // QKV projections on HMMA (bf16x3)
    gemm_hmma_kernel<<<dim3(8, 32, 3), 256, GSMEM>>>(xs, ws, q, k, v);

    // RoPE + norm; Q/K/V emitted as bf16 hi/lo planes
    rope_norm_kernel<<<(BT_ * H_) / 8, 256>>>(
        q, k, v, sqk, (__nv_bfloat16*)qn, (__nv_bfloat16*)kn, (__nv_bfloat16*)vn);

    // Flash attention (S and PV on HMMA bf16x3, 64-row q-tiles,
    // epilogue emits att directly as bf16 hi/lo planes)
    attn_kernel<<<dim3(T_ / 64, BH_), 256, AT_SM>>>(
        (const __nv_bfloat16*)qn, (const __nv_bfloat16*)kn,
        (const __nv_bfloat16*)vn, as);

    // Wo projection on HMMA (att split fused into attention epilogue)
    gemm_hmma_kernel<<<dim3(8, 32, 1), 256, GSMEM>>>(as, ws + (size_t)3 * 2 * WELEM,
                                                     out, out, out);
}